// round 13
// baseline (speedup 1.0000x reference)
#include <cuda_runtime.h>
#include <cuda_bf16.h>
#include <math.h>
#include <stdint.h>

#define Bsz 2
#define Sseq 2048
#define Dm 2048
#define Hh 16
#define DHd 128
#define QP 1024
#define KVP 1365
#define ROPE 64
#define CKV_W (KVP + ROPE)    // 1429
#define KVUP_W (Dm + Hh * 64) // 3072
#define ROWS (Bsz * Sseq)     // 4096
#define KVP_PAD 1408
#define CKV_NPAD 1536

// ---------------- scratch (device globals; no allocations) ------------------
__device__ __align__(256) __nv_bfloat16 g_qh [(size_t)ROWS * Dm];
__device__ __align__(256) __nv_bfloat16 g_ql [(size_t)ROWS * Dm];
__device__ __align__(256) float         g_cq [(size_t)ROWS * QP];
__device__ __align__(256) __nv_bfloat16 g_cqh[(size_t)ROWS * QP];
__device__ __align__(256) __nv_bfloat16 g_cql[(size_t)ROWS * QP];
__device__ __align__(256) float         g_Q  [(size_t)ROWS * Dm];
__device__ __align__(256) __nv_bfloat16 g_kvh[(size_t)ROWS * KVP_PAD];
__device__ __align__(256) __nv_bfloat16 g_kvl[(size_t)ROWS * KVP_PAD];
__device__ __align__(256) float         g_KV [(size_t)ROWS * KVUP_W];
__device__ __align__(256) __nv_bfloat16 g_aoh[(size_t)ROWS * Dm];
__device__ __align__(256) __nv_bfloat16 g_aol[(size_t)ROWS * Dm];
// attention operand buffers (bf16 hi/lo, head-contiguous [row][h*128+d])
__device__ __align__(256) __nv_bfloat16 g_Qhb[(size_t)ROWS * Dm];
__device__ __align__(256) __nv_bfloat16 g_Qlb[(size_t)ROWS * Dm];
__device__ __align__(256) __nv_bfloat16 g_Khb[(size_t)ROWS * Dm];
__device__ __align__(256) __nv_bfloat16 g_Klb[(size_t)ROWS * Dm];
__device__ __align__(256) __nv_bfloat16 g_Vhb[(size_t)ROWS * Dm];
__device__ __align__(256) __nv_bfloat16 g_Vlb[(size_t)ROWS * Dm];
// weights
__device__ __align__(256) __nv_bfloat16 g_wdqh [(size_t)QP * Dm];
__device__ __align__(256) __nv_bfloat16 g_wdql [(size_t)QP * Dm];
__device__ __align__(256) __nv_bfloat16 g_wuqh [(size_t)Dm * QP];
__device__ __align__(256) __nv_bfloat16 g_wuql [(size_t)Dm * QP];
__device__ __align__(256) __nv_bfloat16 g_wdkvh[(size_t)CKV_NPAD * Dm];
__device__ __align__(256) __nv_bfloat16 g_wdkvl[(size_t)CKV_NPAD * Dm];
__device__ __align__(256) __nv_bfloat16 g_wukvh[(size_t)KVUP_W * KVP_PAD];
__device__ __align__(256) __nv_bfloat16 g_wukvl[(size_t)KVUP_W * KVP_PAD];
__device__ __align__(256) __nv_bfloat16 g_woh  [(size_t)Dm * Dm];
__device__ __align__(256) __nv_bfloat16 g_wol  [(size_t)Dm * Dm];

// ---------------- PTX helpers -------------------------------------------------
__device__ __forceinline__ uint32_t smem_u32(const void* p) {
    uint32_t a;
    asm("{ .reg .u64 t; cvta.to.shared.u64 t, %1; cvt.u32.u64 %0, t; }" : "=r"(a) : "l"(p));
    return a;
}
#define LDSM_X4(r, ad) \
    asm volatile("ldmatrix.sync.aligned.m8n8.x4.shared.b16 {%0,%1,%2,%3}, [%4];" \
        : "=r"((r)[0]), "=r"((r)[1]), "=r"((r)[2]), "=r"((r)[3]) : "r"(ad))
#define LDSM_X2(r, ad) \
    asm volatile("ldmatrix.sync.aligned.m8n8.x2.shared.b16 {%0,%1}, [%2];" \
        : "=r"((r)[0]), "=r"((r)[1]) : "r"(ad))
#define LDSM_X2_T(r, ad) \
    asm volatile("ldmatrix.sync.aligned.m8n8.x2.trans.shared.b16 {%0,%1}, [%2];" \
        : "=r"((r)[0]), "=r"((r)[1]) : "r"(ad))
#define MMA_BF16(d, a, b0, b1) \
    asm volatile("mma.sync.aligned.m16n8k16.row.col.f32.bf16.bf16.f32 " \
        "{%0,%1,%2,%3},{%4,%5,%6,%7},{%8,%9},{%0,%1,%2,%3};" \
        : "+f"((d)[0]), "+f"((d)[1]), "+f"((d)[2]), "+f"((d)[3]) \
        : "r"((a)[0]), "r"((a)[1]), "r"((a)[2]), "r"((a)[3]), "r"(b0), "r"(b1))
#define CP_ASYNC16(sa, ga) \
    asm volatile("cp.async.cg.shared.global [%0], [%1], 16;" :: "r"(sa), "l"(ga))
#define CP_COMMIT() asm volatile("cp.async.commit_group;" ::: "memory")
#define CP_WAIT(n)  asm volatile("cp.async.wait_group %0;" :: "n"(n) : "memory")

// ---------------- HMMA split-bf16 GEMM (k-chunk 64, term-outer MMA order) ------
#define TILE_BYTES 18432          // 128 rows * 144B (64 bf16 + 16B pad)
#define STG_BYTES  (4 * TILE_BYTES)
#define GEMM_SMEM  (2 * STG_BYTES)   // 147456

__global__ __launch_bounds__(256) void hmma_gemm(
    const __nv_bfloat16* __restrict__ Ahi, const __nv_bfloat16* __restrict__ Alo,
    const __nv_bfloat16* __restrict__ Bhi, const __nv_bfloat16* __restrict__ Blo,
    float* __restrict__ C, int Kp, int Nreal, int ldc)
{
    extern __shared__ char smm[];
    const uint32_t sbase = smem_u32(smm);
    const int tid = threadIdx.x, lane = tid & 31, wid = tid >> 5;
    const int m0 = blockIdx.y * 128, n0 = blockIdx.x * 128;
    const int wm = wid >> 2, wn = wid & 3;
    const __nv_bfloat16* srcs[4] = { Ahi, Alo, Bhi, Blo };

    float acc[4][4][4];
#pragma unroll
    for (int i = 0; i < 4; i++)
#pragma unroll
        for (int j = 0; j < 4; j++)
#pragma unroll
            for (int q = 0; q < 4; q++) acc[i][j][q] = 0.f;

    const int nch = Kp >> 6;

    auto issue = [&](int c) {
        const int s = c & 1;
        const int k0 = c << 6;
#pragma unroll
        for (int t = 0; t < 4; t++) {
            const int row0 = (t < 2) ? m0 : n0;
            const uint32_t sb = sbase + (uint32_t)(s * 4 + t) * TILE_BYTES;
#pragma unroll
            for (int it = 0; it < 4; it++) {
                const int idx = tid + it * 256;
                const int r = idx >> 3, seg = idx & 7;
                CP_ASYNC16(sb + r * 144 + seg * 16,
                           srcs[t] + (size_t)(row0 + r) * Kp + k0 + seg * 8);
            }
        }
        CP_COMMIT();
    };

    issue(0);

    const int a_row = wm * 64 + (lane & 15);
    const int a_colh = (lane >> 4) << 3;
    const int b_row = wn * 32 + (lane & 7);
    const int b_colh = (((lane >> 3) & 1) << 3);

    for (int c = 0; c < nch; c++) {
        const int s = c & 1;
        if (c + 1 < nch) { issue(c + 1); CP_WAIT(1); }
        else             { CP_WAIT(0); }
        __syncthreads();

        const uint32_t sAh = sbase + (uint32_t)(s * 4 + 0) * TILE_BYTES;
        const uint32_t sAl = sbase + (uint32_t)(s * 4 + 1) * TILE_BYTES;
        const uint32_t sBh = sbase + (uint32_t)(s * 4 + 2) * TILE_BYTES;
        const uint32_t sBl = sbase + (uint32_t)(s * 4 + 3) * TILE_BYTES;

#pragma unroll
        for (int ks = 0; ks < 4; ks++) {
            uint32_t ah[4][4], al[4][4], bh[4][2], bl[4][2];
            const int acol = ks * 16 + a_colh;
#pragma unroll
            for (int mi = 0; mi < 4; mi++) {
                const uint32_t off = (uint32_t)(a_row + mi * 16) * 144 + acol * 2;
                LDSM_X4(ah[mi], sAh + off);
                LDSM_X4(al[mi], sAl + off);
            }
            const int bcol = ks * 16 + b_colh;
#pragma unroll
            for (int ni = 0; ni < 4; ni++) {
                const uint32_t off = (uint32_t)(b_row + ni * 8) * 144 + bcol * 2;
                LDSM_X2(bh[ni], sBh + off);
                LDSM_X2(bl[ni], sBl + off);
            }
            // term-outer order: 16 independent accumulators between reuse
#pragma unroll
            for (int mi = 0; mi < 4; mi++)
#pragma unroll
                for (int ni = 0; ni < 4; ni++)
                    MMA_BF16(acc[mi][ni], ah[mi], bh[ni][0], bh[ni][1]);
#pragma unroll
            for (int mi = 0; mi < 4; mi++)
#pragma unroll
                for (int ni = 0; ni < 4; ni++)
                    MMA_BF16(acc[mi][ni], ah[mi], bl[ni][0], bl[ni][1]);
#pragma unroll
            for (int mi = 0; mi < 4; mi++)
#pragma unroll
                for (int ni = 0; ni < 4; ni++)
                    MMA_BF16(acc[mi][ni], al[mi], bh[ni][0], bh[ni][1]);
        }
        __syncthreads();
    }

#pragma unroll
    for (int mi = 0; mi < 4; mi++) {
        const int row = m0 + wm * 64 + mi * 16 + (lane >> 2);
#pragma unroll
        for (int ni = 0; ni < 4; ni++) {
            const int col = n0 + wn * 32 + ni * 8 + (lane & 3) * 2;
            float* p0 = C + (size_t)row * ldc + col;
            float* p1 = C + (size_t)(row + 8) * ldc + col;
            if (col < Nreal)     { p0[0] = acc[mi][ni][0]; p1[0] = acc[mi][ni][2]; }
            if (col + 1 < Nreal) { p0[1] = acc[mi][ni][1]; p1[1] = acc[mi][ni][3]; }
        }
    }
}

// ---------------- split / transpose-split kernels -----------------------------
__global__ void split_kernel(const float* __restrict__ in,
                             __nv_bfloat16* __restrict__ hi, __nv_bfloat16* __restrict__ lo,
                             long total, int w, int wp)
{
    for (long idx = (long)blockIdx.x * blockDim.x + threadIdx.x; idx < total;
         idx += (long)gridDim.x * blockDim.x) {
        long r = idx / wp;
        int c = (int)(idx - r * wp);
        float v = (c < w) ? in[r * (long)w + c] : 0.f;
        __nv_bfloat16 h = __float2bfloat16(v);
        hi[idx] = h;
        lo[idx] = __float2bfloat16(v - __bfloat162float(h));
    }
}

__global__ void tsplit_kernel(const float* __restrict__ W,
                              __nv_bfloat16* __restrict__ hi, __nv_bfloat16* __restrict__ lo,
                              int K, int N, int Kp)
{
    __shared__ float t[32][33];
    int k0 = blockIdx.x * 32, n0 = blockIdx.y * 32;
    for (int i = threadIdx.y; i < 32; i += 8) {
        int k = k0 + i, n = n0 + threadIdx.x;
        t[i][threadIdx.x] = (k < K && n < N) ? W[(size_t)k * N + n] : 0.f;
    }
    __syncthreads();
    for (int i = threadIdx.y; i < 32; i += 8) {
        int n = n0 + i, k = k0 + threadIdx.x;
        float v = t[threadIdx.x][i];
        __nv_bfloat16 h = __float2bfloat16(v);
        size_t o = (size_t)n * Kp + k;
        hi[o] = h;
        lo[o] = __float2bfloat16(v - __bfloat162float(h));
    }
}

// ---------------- LayerNorm fused with split+pad ------------------------------
__global__ __launch_bounds__(256) void ln_split_kernel(
    const float* __restrict__ in, const float* __restrict__ w, const float* __restrict__ bb,
    __nv_bfloat16* __restrict__ hi, __nv_bfloat16* __restrict__ lo,
    int width, int inStride, int wp)
{
    int row = blockIdx.x;
    const float* x = in + (size_t)row * inStride;
    float s = 0.f, s2 = 0.f;
    for (int i = threadIdx.x; i < width; i += 256) { float v = x[i]; s += v; s2 += v * v; }
    __shared__ float sh[64];
#pragma unroll
    for (int o = 16; o > 0; o >>= 1) {
        s  += __shfl_down_sync(0xffffffffu, s,  o);
        s2 += __shfl_down_sync(0xffffffffu, s2, o);
    }
    int wid = threadIdx.x >> 5, lid = threadIdx.x & 31;
    if (lid == 0) { sh[wid] = s; sh[32 + wid] = s2; }
    __syncthreads();
    if (threadIdx.x == 0) {
        float ts = 0.f, ts2 = 0.f;
        for (int i = 0; i < 8; i++) { ts += sh[i]; ts2 += sh[32 + i]; }
        sh[0] = ts; sh[32] = ts2;
    }
    __syncthreads();
    float mean = sh[0] / width;
    float var = sh[32] / width - mean * mean;
    float inv = rsqrtf(var + 1e-5f);
    for (int i = threadIdx.x; i < wp; i += 256) {
        float y = 0.f;
        if (i < width) y = (x[i] - mean) * inv * w[i] + bb[i];
        __nv_bfloat16 h = __float2bfloat16(y);
        size_t o = (size_t)row * wp + i;
        hi[o] = h;
        lo[o] = __float2bfloat16(y - __bfloat162float(h));
    }
}

// ---------------- RoPE + split prep kernels ------------------------------------
__device__ __forceinline__ void rope_cs(int s, int j, float& c, float& sn) {
    float fr = powf(10000.f, -(float)(2 * j) / 128.f);
    float ang = (float)s * fr;
    sn = sinf(ang); c = cosf(ang);
}
__device__ __forceinline__ void wsplit(__nv_bfloat16* hi, __nv_bfloat16* lo, size_t o, float v) {
    __nv_bfloat16 h = __float2bfloat16(v);
    hi[o] = h;
    lo[o] = __float2bfloat16(v - __bfloat162float(h));
}

__global__ void qprep_kernel(const float* __restrict__ Qf,
                             __nv_bfloat16* __restrict__ hi, __nv_bfloat16* __restrict__ lo)
{
    int row = blockIdx.x, h = blockIdx.y, j = threadIdx.x;  // 64 threads
    int s = row & (Sseq - 1);
    size_t base = (size_t)row * Dm + h * DHd;
    wsplit(hi, lo, base + j, Qf[base + j]);
    if (j < 32) {
        float c, sn; rope_cs(s, j, c, sn);
        float x1 = Qf[base + 64 + j], x2 = Qf[base + 96 + j];
        wsplit(hi, lo, base + 64 + j, x1 * c - x2 * sn);
        wsplit(hi, lo, base + 96 + j, x2 * c + x1 * sn);
    }
}

__global__ void kprep_kernel(const float* __restrict__ KVf, const float* __restrict__ ckv,
                             __nv_bfloat16* __restrict__ hi, __nv_bfloat16* __restrict__ lo)
{
    int row = blockIdx.x, h = blockIdx.y, j = threadIdx.x;  // 64 threads
    int s = row & (Sseq - 1);
    size_t ob = (size_t)row * Dm + h * DHd;
    wsplit(hi, lo, ob + j, KVf[(size_t)row * KVUP_W + h * 192 + j]);
    if (j < 32) {
        float c, sn; rope_cs(s, j, c, sn);
        const float* src = ckv + (size_t)row * CKV_W + KVP;
        float x1 = src[j], x2 = src[j + 32];
        wsplit(hi, lo, ob + 64 + j, x1 * c - x2 * sn);
        wsplit(hi, lo, ob + 96 + j, x2 * c + x1 * sn);
    }
}

__global__ void vprep_kernel(const float* __restrict__ KVf,
                             __nv_bfloat16* __restrict__ hi, __nv_bfloat16* __restrict__ lo)
{
    int row = blockIdx.x, h = blockIdx.y, d = threadIdx.x;  // 128 threads
    wsplit(hi, lo, (size_t)row * Dm + h * DHd + d, KVf[(size_t)row * KVUP_W + h * 192 + 64 + d]);
}

// ---------------- HMMA flash attention (double-buffered K/V) -------------------
#define AQ_H 0
#define AQ_L 20480
#define AKV  40960
#define KV_STRIDE 75776
#define A_SS 192512
#define A_PH 209920
#define A_PL 219136
#define A_M  228352
#define A_L  228608
#define A_A  228864
#define ATT_SMEM 229120

__global__ __launch_bounds__(256) void attn_hmma(
    const __nv_bfloat16* __restrict__ Qh, const __nv_bfloat16* __restrict__ Ql,
    const __nv_bfloat16* __restrict__ Kh, const __nv_bfloat16* __restrict__ Kl,
    const __nv_bfloat16* __restrict__ Vh, const __nv_bfloat16* __restrict__ Vl,
    __nv_bfloat16* __restrict__ Oh, __nv_bfloat16* __restrict__ Ol)
{
    extern __shared__ char sm[];
    const uint32_t sb = smem_u32(sm);
    float* mrow = (float*)(sm + A_M);
    float* lrow = (float*)(sm + A_L);
    float* arow = (float*)(sm + A_A);
    float* Ss   = (float*)(sm + A_SS);

    const int qt = blockIdx.x, h = blockIdx.y, b = blockIdx.z;
    const int q0 = qt * 64;
    const int tid = threadIdx.x, lane = tid & 31, wid = tid >> 5;
    const int wm = wid >> 1, wn = wid & 1;
    const float scale = 0.08838834764831845f;

    {
        const __nv_bfloat16* g0[2] = { Qh, Ql };
#pragma unroll
        for (int part = 0; part < 2; part++) {
            const uint32_t base = sb + AQ_H + part * 20480;
#pragma unroll
            for (int i = 0; i < 4; i++) {
                int idx = tid + i * 256;
                int r = idx >> 4, s = idx & 15;
                uint32_t sa = base + (s >> 2) * 5120 + r * 80 + (s & 3) * 16;
                const __nv_bfloat16* g = g0[part] + (size_t)(b * Sseq + q0 + r) * Dm + h * DHd + s * 8;
                CP_ASYNC16(sa, g);
            }
        }
    }

    const __nv_bfloat16* gk[2] = { Kh, Kl };
    const __nv_bfloat16* gv[2] = { Vh, Vl };
    auto issue_kv = [&](int kt) {
        const int k0 = kt * 64;
        const uint32_t stg = sb + AKV + (uint32_t)(kt & 1) * KV_STRIDE;
#pragma unroll
        for (int part = 0; part < 2; part++) {
            const uint32_t kb = stg + part * 20480;
            const uint32_t vb = stg + 40960 + part * 17408;
#pragma unroll
            for (int i = 0; i < 4; i++) {
                int idx = tid + i * 256;
                int r = idx >> 4, s = idx & 15;
                size_t grow = (size_t)(b * Sseq + k0 + r) * Dm + h * DHd + s * 8;
                CP_ASYNC16(kb + (s >> 2) * 5120 + r * 80 + (s & 3) * 16, gk[part] + grow);
                CP_ASYNC16(vb + r * 272 + s * 16, gv[part] + grow);
            }
        }
        CP_COMMIT();
    };

    if (tid < 64) { mrow[tid] = -INFINITY; lrow[tid] = 0.f; }

    float o[8][4];
#pragma unroll
    for (int i = 0; i < 8; i++)
#pragma unroll
        for (int j = 0; j < 4; j++) o[i][j] = 0.f;

    const int nkt = qt + 1;
    issue_kv(0);

    for (int kt = 0; kt < nkt; kt++) {
        const int k0 = kt * 64;
        if (kt + 1 < nkt) { issue_kv(kt + 1); CP_WAIT(1); }
        else              { CP_WAIT(0); }
        __syncthreads();

        const uint32_t stg = sb + AKV + (uint32_t)(kt & 1) * KV_STRIDE;
        const uint32_t sKh = stg, sKl = stg + 20480;
        const uint32_t sVh = stg + 40960, sVl = stg + 58368;

        float s4[4][4];
#pragma unroll
        for (int i = 0; i < 4; i++)
#pragma unroll
            for (int j = 0; j < 4; j++) s4[i][j] = 0.f;

#pragma unroll
        for (int ks = 0; ks < 8; ks++) {
            uint32_t ah[4], al[4], bh[4][2], bl[4][2];
            const int chunk = ks >> 1;
            const uint32_t aoff = (uint32_t)(wm * 16 + (lane & 15)) * 80 +
                                  ((ks & 1) * 16 + ((lane >> 4) << 3)) * 2;
            LDSM_X4(ah, sb + AQ_H + chunk * 5120 + aoff);
            LDSM_X4(al, sb + AQ_L + chunk * 5120 + aoff);
#pragma unroll
            for (int nf = 0; nf < 4; nf++) {
                const uint32_t boff = (uint32_t)(wn * 32 + nf * 8 + (lane & 7)) * 80 +
                                      ((ks & 1) * 16 + (((lane >> 3) & 1) << 3)) * 2;
                LDSM_X2(bh[nf], sKh + chunk * 5120 + boff);
                LDSM_X2(bl[nf], sKl + chunk * 5120 + boff);
            }
            // term-outer: 4 independent accs between reuse
#pragma unroll
            for (int nf = 0; nf < 4; nf++) MMA_BF16(s4[nf], ah, bh[nf][0], bh[nf][1]);
#pragma unroll
            for (int nf = 0; nf < 4; nf++) MMA_BF16(s4[nf], ah, bl[nf][0], bl[nf][1]);
#pragma unroll
            for (int nf = 0; nf < 4; nf++) MMA_BF16(s4[nf], al, bh[nf][0], bh[nf][1]);
        }
        {
            const int r0 = wm * 16 + (lane >> 2);
#pragma unroll
            for (int nf = 0; nf < 4; nf++) {
                const int c0 = wn * 32 + nf * 8 + (lane & 3) * 2;
#pragma unroll
                for (int e = 0; e < 4; e++) {
                    int r = r0 + (e >> 1) * 8;
                    int c = c0 + (e & 1);
                    float v = (k0 + c <= q0 + r) ? s4[nf][e] * scale : -INFINITY;
                    Ss[r * 68 + c] = v;
                }
            }
        }
        __syncthreads();

        {
            const int r = tid >> 2, cs = (tid & 3) * 16;
            float mx = -INFINITY;
#pragma unroll
            for (int j = 0; j < 16; j++) mx = fmaxf(mx, Ss[r * 68 + cs + j]);
            mx = fmaxf(mx, __shfl_xor_sync(0xffffffffu, mx, 1));
            mx = fmaxf(mx, __shfl_xor_sync(0xffffffffu, mx, 2));
            float mold = mrow[r];
            float mnew = fmaxf(mold, mx);
            float sum = 0.f;
            __nv_bfloat16* Ph = (__nv_bfloat16*)(sm + A_PH);
            __nv_bfloat16* Pl = (__nv_bfloat16*)(sm + A_PL);
#pragma unroll
            for (int j = 0; j < 16; j++) {
                float p = __expf(Ss[r * 68 + cs + j] - mnew);
                sum += p;
                __nv_bfloat16 ph = __float2bfloat16(p);
                Ph[r * 72 + cs + j] = ph;
                Pl[r * 72 + cs + j] = __float2bfloat16(p - __bfloat162float(ph));
            }
            sum += __shfl_xor_sync(0xffffffffu, sum, 1);
            sum += __shfl_xor_sync(0xffffffffu, sum, 2);
            if ((tid & 3) == 0) {
                float alpha = __expf(mold - mnew);
                arow[r] = alpha;
                lrow[r] = lrow[r] * alpha + sum;
                mrow[r] = mnew;
            }
        }
        __syncthreads();

        {
            float al0 = arow[wm * 16 + (lane >> 2)];
            float al1 = arow[wm * 16 + (lane >> 2) + 8];
#pragma unroll
            for (int nf = 0; nf < 8; nf++) {
                o[nf][0] *= al0; o[nf][1] *= al0;
                o[nf][2] *= al1; o[nf][3] *= al1;
            }
        }

#pragma unroll
        for (int ks = 0; ks < 4; ks++) {
            uint32_t ah[4], al[4], bh[8][2], bl[8][2];
            const uint32_t aoff = (uint32_t)(wm * 16 + (lane & 15)) * 144 +
                                  (ks * 16 + ((lane >> 4) << 3)) * 2;
            LDSM_X4(ah, sb + A_PH + aoff);
            LDSM_X4(al, sb + A_PL + aoff);
            const int vrow = ks * 16 + (lane & 7) + ((lane >> 3) & 1) * 8;
#pragma unroll
            for (int nf = 0; nf < 8; nf++) {
                const uint32_t boff = (uint32_t)vrow * 272 + (wn * 64 + nf * 8) * 2;
                LDSM_X2_T(bh[nf], sVh + boff);
                LDSM_X2_T(bl[nf], sVl + boff);
            }
            // term-outer: 8 independent accs between reuse
#pragma unroll
            for (int nf = 0; nf < 8; nf++) MMA_BF16(o[nf], ah, bh[nf][0], bh[nf][1]);
#pragma unroll
            for (int nf = 0; nf < 8; nf++) MMA_BF16(o[nf], ah, bl[nf][0], bl[nf][1]);
#pragma unroll
            for (int nf = 0; nf < 8; nf++) MMA_BF16(o[nf], al, bh[nf][0], bh[nf][1]);
        }
        __syncthreads();
    }

    {
        const int r0 = wm * 16 + (lane >> 2);
        const float inv0 = 1.f / lrow[r0];
        const float inv1 = 1.f / lrow[r0 + 8];
#pragma unroll
        for (int nf = 0; nf < 8; nf++) {
            const int c = wn * 64 + nf * 8 + (lane & 3) * 2;
            size_t g0 = (size_t)(b * Sseq + q0 + r0) * Dm + h * DHd + c;
            size_t g1 = (size_t)(b * Sseq + q0 + r0 + 8) * Dm + h * DHd + c;
            wsplit(Oh, Ol, g0,     o[nf][0] * inv0);
            wsplit(Oh, Ol, g0 + 1, o[nf][1] * inv0);
            wsplit(Oh, Ol, g1,     o[nf][2] * inv1);
            wsplit(Oh, Ol, g1 + 1, o[nf][3] * inv1);
        }
    }
}

// ---------------- host launcher -------------------------------------------------
extern "C" void kernel_launch(void* const* d_in, const int* in_sizes, int n_in,
                              void* d_out, int out_size)
{
    const float* query   = (const float*)d_in[0];
    const float* W_dq    = (const float*)d_in[1];
    const float* W_uq    = (const float*)d_in[2];
    const float* q_ln_w  = (const float*)d_in[3];
    const float* q_ln_b  = (const float*)d_in[4];
    const float* W_dkv   = (const float*)d_in[5];
    const float* W_ukv   = (const float*)d_in[6];
    const float* kv_ln_w = (const float*)d_in[7];
    const float* kv_ln_b = (const float*)d_in[8];
    const float* W_o     = (const float*)d_in[9];

    float* out = (float*)d_out;
    float* ckv = out + (size_t)ROWS * Dm;

    __nv_bfloat16 *qh, *ql, *cqh, *cql, *kvh, *kvl, *aoh, *aol;
    __nv_bfloat16 *Qhb, *Qlb, *Khb, *Klb, *Vhb, *Vlb;
    __nv_bfloat16 *wdqh, *wdql, *wuqh, *wuql, *wdkvh, *wdkvl, *wukvh, *wukvl, *woh, *wol;
    float *cq, *Qf, *KVf;
    cudaGetSymbolAddress((void**)&qh, g_qh);       cudaGetSymbolAddress((void**)&ql, g_ql);
    cudaGetSymbolAddress((void**)&cq, g_cq);
    cudaGetSymbolAddress((void**)&cqh, g_cqh);     cudaGetSymbolAddress((void**)&cql, g_cql);
    cudaGetSymbolAddress((void**)&Qf, g_Q);
    cudaGetSymbolAddress((void**)&kvh, g_kvh);     cudaGetSymbolAddress((void**)&kvl, g_kvl);
    cudaGetSymbolAddress((void**)&KVf, g_KV);
    cudaGetSymbolAddress((void**)&aoh, g_aoh);     cudaGetSymbolAddress((void**)&aol, g_aol);
    cudaGetSymbolAddress((void**)&Qhb, g_Qhb);     cudaGetSymbolAddress((void**)&Qlb, g_Qlb);
    cudaGetSymbolAddress((void**)&Khb, g_Khb);     cudaGetSymbolAddress((void**)&Klb, g_Klb);
    cudaGetSymbolAddress((void**)&Vhb, g_Vhb);     cudaGetSymbolAddress((void**)&Vlb, g_Vlb);
    cudaGetSymbolAddress((void**)&wdqh, g_wdqh);   cudaGetSymbolAddress((void**)&wdql, g_wdql);
    cudaGetSymbolAddress((void**)&wuqh, g_wuqh);   cudaGetSymbolAddress((void**)&wuql, g_wuql);
    cudaGetSymbolAddress((void**)&wdkvh, g_wdkvh); cudaGetSymbolAddress((void**)&wdkvl, g_wdkvl);
    cudaGetSymbolAddress((void**)&wukvh, g_wukvh); cudaGetSymbolAddress((void**)&wukvl, g_wukvl);
    cudaGetSymbolAddress((void**)&woh, g_woh);     cudaGetSymbolAddress((void**)&wol, g_wol);

    cudaFuncSetAttribute(hmma_gemm, cudaFuncAttributeMaxDynamicSharedMemorySize, GEMM_SMEM);
    cudaFuncSetAttribute(attn_hmma, cudaFuncAttributeMaxDynamicSharedMemorySize, ATT_SMEM);

    static cudaStream_t s2 = 0;
    static cudaEvent_t evFork = 0, evJoin = 0;
    if (s2 == 0) {
        cudaStreamCreateWithFlags(&s2, cudaStreamNonBlocking);
        cudaEventCreateWithFlags(&evFork, cudaEventDisableTiming);
        cudaEventCreateWithFlags(&evJoin, cudaEventDisableTiming);
    }

    // ---- stream 0 (legacy): q path. launch index 3 = hmma_gemm (ncu target)
    {
        long tq = (long)ROWS * Dm;
        split_kernel<<<(int)((tq + 255) / 256), 256>>>(query, qh, ql, tq, Dm, Dm);  // 0
    }
    cudaEventRecord(evFork, 0);
    tsplit_kernel<<<dim3(Dm / 32, QP / 32), dim3(32, 8)>>>(W_dq, wdqh, wdql, Dm, QP, Dm); // 1
    tsplit_kernel<<<dim3(QP / 32, Dm / 32), dim3(32, 8)>>>(W_uq, wuqh, wuql, QP, Dm, QP); // 2
    hmma_gemm<<<dim3(QP / 128, ROWS / 128), 256, GEMM_SMEM>>>(qh, ql, wdqh, wdql, cq, Dm, QP, QP); // 3 <- ncu
    ln_split_kernel<<<ROWS, 256>>>(cq, q_ln_w, q_ln_b, cqh, cql, QP, QP, QP);
    hmma_gemm<<<dim3(Dm / 128, ROWS / 128), 256, GEMM_SMEM>>>(cqh, cql, wuqh, wuql, Qf, QP, Dm, Dm);
    qprep_kernel<<<dim3(ROWS, Hh), 64, 0>>>(Qf, Qhb, Qlb);

    // ---- stream s2: kv path (depends only on qh/ql via evFork)
    cudaStreamWaitEvent(s2, evFork, 0);
    tsplit_kernel<<<dim3(Dm / 32, CKV_NPAD / 32), dim3(32, 8), 0, s2>>>(W_dkv, wdkvh, wdkvl, Dm, CKV_W, Dm);
    hmma_gemm<<<dim3(CKV_NPAD / 128, ROWS / 128), 256, GEMM_SMEM, s2>>>(qh, ql, wdkvh, wdkvl, ckv, Dm, CKV_W, CKV_W);
    ln_split_kernel<<<ROWS, 256, 0, s2>>>(ckv, kv_ln_w, kv_ln_b, kvh, kvl, KVP, CKV_W, KVP_PAD);
    tsplit_kernel<<<dim3(KVP_PAD / 32, KVUP_W / 32), dim3(32, 8), 0, s2>>>(W_ukv, wukvh, wukvl, KVP, KVUP_W, KVP_PAD);
    hmma_gemm<<<dim3(KVUP_W / 128, ROWS / 128), 256, GEMM_SMEM, s2>>>(kvh, kvl, wukvh, wukvl, KVf, KVP_PAD, KVUP_W, KVUP_W);
    kprep_kernel<<<dim3(ROWS, Hh), 64, 0, s2>>>(KVf, ckv, Khb, Klb);
    vprep_kernel<<<dim3(ROWS, Hh), 128, 0, s2>>>(KVf, Vhb, Vlb);
    {
        long tw = (long)Dm * Dm;
        split_kernel<<<(int)((tw + 255) / 256), 256, 0, s2>>>(W_o, woh, wol, tw, Dm, Dm);
    }
    cudaEventRecord(evJoin, s2);

    // ---- join on stream 0: attention + output projection
    cudaStreamWaitEvent(0, evJoin, 0);
    attn_hmma<<<dim3(Sseq / 64, Hh, Bsz), 256, ATT_SMEM>>>(Qhb, Qlb, Khb, Klb, Vhb, Vlb, aoh, aol);
    hmma_gemm<<<dim3(Dm / 128, ROWS / 128), 256, GEMM_SMEM>>>(aoh, aol, woh, wol, out, Dm, Dm, Dm);
}

// round 14
// speedup vs baseline: 1.1984x; 1.1984x over previous
#include <cuda_runtime.h>
#include <cuda_bf16.h>
#include <cuda_fp16.h>
#include <math.h>
#include <stdint.h>

#define Bsz 2
#define Sseq 2048
#define Dm 2048
#define Hh 16
#define DHd 128
#define QP 1024
#define KVP 1365
#define ROPE 64
#define CKV_W (KVP + ROPE)    // 1429
#define KVUP_W (Dm + Hh * 64) // 3072
#define ROWS (Bsz * Sseq)     // 4096
#define KVP_PAD 1408
#define CKV_NPAD 1536

// ---------------- scratch (device globals; no allocations) ------------------
__device__ __align__(256) __half g_qh16 [(size_t)ROWS * Dm];
__device__ __align__(256) __half g_ql16 [(size_t)ROWS * Dm];
__device__ __align__(256) float  g_cq   [(size_t)ROWS * QP];
__device__ __align__(256) __half g_cqh16[(size_t)ROWS * QP];
__device__ __align__(256) __half g_cql16[(size_t)ROWS * QP];
__device__ __align__(256) float  g_Q    [(size_t)ROWS * Dm];
__device__ __align__(256) __half g_kvh16[(size_t)ROWS * KVP_PAD];
__device__ __align__(256) __half g_kvl16[(size_t)ROWS * KVP_PAD];
__device__ __align__(256) float  g_KV   [(size_t)ROWS * KVUP_W];
__device__ __align__(256) __half g_aoh16[(size_t)ROWS * Dm];
__device__ __align__(256) __half g_aol16[(size_t)ROWS * Dm];
// attention operand buffers (bf16 hi/lo, head-contiguous [row][h*128+d])
__device__ __align__(256) __nv_bfloat16 g_Qhb[(size_t)ROWS * Dm];
__device__ __align__(256) __nv_bfloat16 g_Qlb[(size_t)ROWS * Dm];
__device__ __align__(256) __nv_bfloat16 g_Khb[(size_t)ROWS * Dm];
__device__ __align__(256) __nv_bfloat16 g_Klb[(size_t)ROWS * Dm];
__device__ __align__(256) __nv_bfloat16 g_Vhb[(size_t)ROWS * Dm];
__device__ __align__(256) __nv_bfloat16 g_Vlb[(size_t)ROWS * Dm];
// weights: single fp16, transposed [N][Kp]
__device__ __align__(256) __half g_wdq16 [(size_t)QP * Dm];
__device__ __align__(256) __half g_wuq16 [(size_t)Dm * QP];
__device__ __align__(256) __half g_wdkv16[(size_t)CKV_NPAD * Dm];
__device__ __align__(256) __half g_wukv16[(size_t)KVUP_W * KVP_PAD];
__device__ __align__(256) __half g_wo16  [(size_t)Dm * Dm];

// ---------------- PTX helpers -------------------------------------------------
__device__ __forceinline__ uint32_t smem_u32(const void* p) {
    uint32_t a;
    asm("{ .reg .u64 t; cvta.to.shared.u64 t, %1; cvt.u32.u64 %0, t; }" : "=r"(a) : "l"(p));
    return a;
}
#define LDSM_X4(r, ad) \
    asm volatile("ldmatrix.sync.aligned.m8n8.x4.shared.b16 {%0,%1,%2,%3}, [%4];" \
        : "=r"((r)[0]), "=r"((r)[1]), "=r"((r)[2]), "=r"((r)[3]) : "r"(ad))
#define LDSM_X2(r, ad) \
    asm volatile("ldmatrix.sync.aligned.m8n8.x2.shared.b16 {%0,%1}, [%2];" \
        : "=r"((r)[0]), "=r"((r)[1]) : "r"(ad))
#define LDSM_X2_T(r, ad) \
    asm volatile("ldmatrix.sync.aligned.m8n8.x2.trans.shared.b16 {%0,%1}, [%2];" \
        : "=r"((r)[0]), "=r"((r)[1]) : "r"(ad))
#define MMA_BF16(d, a, b0, b1) \
    asm volatile("mma.sync.aligned.m16n8k16.row.col.f32.bf16.bf16.f32 " \
        "{%0,%1,%2,%3},{%4,%5,%6,%7},{%8,%9},{%0,%1,%2,%3};" \
        : "+f"((d)[0]), "+f"((d)[1]), "+f"((d)[2]), "+f"((d)[3]) \
        : "r"((a)[0]), "r"((a)[1]), "r"((a)[2]), "r"((a)[3]), "r"(b0), "r"(b1))
#define MMA_F16(d, a, b0, b1) \
    asm volatile("mma.sync.aligned.m16n8k16.row.col.f32.f16.f16.f32 " \
        "{%0,%1,%2,%3},{%4,%5,%6,%7},{%8,%9},{%0,%1,%2,%3};" \
        : "+f"((d)[0]), "+f"((d)[1]), "+f"((d)[2]), "+f"((d)[3]) \
        : "r"((a)[0]), "r"((a)[1]), "r"((a)[2]), "r"((a)[3]), "r"(b0), "r"(b1))
#define CP_ASYNC16(sa, ga) \
    asm volatile("cp.async.cg.shared.global [%0], [%1], 16;" :: "r"(sa), "l"(ga))
#define CP_COMMIT() asm volatile("cp.async.commit_group;" ::: "memory")
#define CP_WAIT(n)  asm volatile("cp.async.wait_group %0;" :: "n"(n) : "memory")

// ---------------- HMMA fp16 GEMM: A = Ah+Al (2x fp16), B = 1x fp16 -------------
// CTA 128x128, 8 warps (2M x 4N), warp tile 64x32, k-chunk 64, 2 stages.
#define TILE_BYTES 18432          // 128 rows * 144B (64 halves + 16B pad)
#define STG_BYTES  (3 * TILE_BYTES)
#define GEMM_SMEM  (2 * STG_BYTES)   // 110592

__global__ __launch_bounds__(256) void hmma_gemm(
    const __half* __restrict__ Ahi, const __half* __restrict__ Alo,
    const __half* __restrict__ B,
    float* __restrict__ C, int Kp, int Nreal, int ldc)
{
    extern __shared__ char smm[];
    const uint32_t sbase = smem_u32(smm);
    const int tid = threadIdx.x, lane = tid & 31, wid = tid >> 5;
    const int m0 = blockIdx.y * 128, n0 = blockIdx.x * 128;
    const int wm = wid >> 2, wn = wid & 3;
    const __half* srcs[3] = { Ahi, Alo, B };

    float acc[4][4][4];
#pragma unroll
    for (int i = 0; i < 4; i++)
#pragma unroll
        for (int j = 0; j < 4; j++)
#pragma unroll
            for (int q = 0; q < 4; q++) acc[i][j][q] = 0.f;

    const int nch = Kp >> 6;

    auto issue = [&](int c) {
        const int s = c & 1;
        const int k0 = c << 6;
#pragma unroll
        for (int t = 0; t < 3; t++) {
            const int row0 = (t < 2) ? m0 : n0;
            const uint32_t sb = sbase + (uint32_t)s * STG_BYTES + (uint32_t)t * TILE_BYTES;
#pragma unroll
            for (int it = 0; it < 4; it++) {
                const int idx = tid + it * 256;
                const int r = idx >> 3, seg = idx & 7;
                CP_ASYNC16(sb + r * 144 + seg * 16,
                           srcs[t] + (size_t)(row0 + r) * Kp + k0 + seg * 8);
            }
        }
        CP_COMMIT();
    };

    issue(0);

    const int a_row = wm * 64 + (lane & 15);
    const int a_colh = (lane >> 4) << 3;
    const int b_row = wn * 32 + (lane & 7);
    const int b_colh = (((lane >> 3) & 1) << 3);

    for (int c = 0; c < nch; c++) {
        const int s = c & 1;
        if (c + 1 < nch) { issue(c + 1); CP_WAIT(1); }
        else             { CP_WAIT(0); }
        __syncthreads();

        const uint32_t sAh = sbase + (uint32_t)s * STG_BYTES;
        const uint32_t sAl = sAh + TILE_BYTES;
        const uint32_t sB  = sAh + 2 * TILE_BYTES;

#pragma unroll
        for (int ks = 0; ks < 4; ks++) {
            uint32_t ah[4][4], al[4][4], bb[4][2];
            const int acol = ks * 16 + a_colh;
#pragma unroll
            for (int mi = 0; mi < 4; mi++) {
                const uint32_t off = (uint32_t)(a_row + mi * 16) * 144 + acol * 2;
                LDSM_X4(ah[mi], sAh + off);
                LDSM_X4(al[mi], sAl + off);
            }
            const int bcol = ks * 16 + b_colh;
#pragma unroll
            for (int ni = 0; ni < 4; ni++) {
                const uint32_t off = (uint32_t)(b_row + ni * 8) * 144 + bcol * 2;
                LDSM_X2(bb[ni], sB + off);
            }
#pragma unroll
            for (int mi = 0; mi < 4; mi++)
#pragma unroll
                for (int ni = 0; ni < 4; ni++)
                    MMA_F16(acc[mi][ni], ah[mi], bb[ni][0], bb[ni][1]);
#pragma unroll
            for (int mi = 0; mi < 4; mi++)
#pragma unroll
                for (int ni = 0; ni < 4; ni++)
                    MMA_F16(acc[mi][ni], al[mi], bb[ni][0], bb[ni][1]);
        }
        __syncthreads();
    }

#pragma unroll
    for (int mi = 0; mi < 4; mi++) {
        const int row = m0 + wm * 64 + mi * 16 + (lane >> 2);
#pragma unroll
        for (int ni = 0; ni < 4; ni++) {
            const int col = n0 + wn * 32 + ni * 8 + (lane & 3) * 2;
            float* p0 = C + (size_t)row * ldc + col;
            float* p1 = C + (size_t)(row + 8) * ldc + col;
            if (col < Nreal)     { p0[0] = acc[mi][ni][0]; p1[0] = acc[mi][ni][2]; }
            if (col + 1 < Nreal) { p0[1] = acc[mi][ni][1]; p1[1] = acc[mi][ni][3]; }
        }
    }
}

// ---------------- split / transpose-split kernels -----------------------------
__device__ __forceinline__ void wsplit16(__half* hi, __half* lo, size_t o, float v) {
    __half h = __float2half_rn(v);
    hi[o] = h;
    lo[o] = __float2half_rn(v - __half2float(h));
}

// fp32 -> 2x fp16 with padding (activations)
__global__ void split2h_kernel(const float* __restrict__ in,
                               __half* __restrict__ hi, __half* __restrict__ lo,
                               long total, int w, int wp)
{
    for (long idx = (long)blockIdx.x * blockDim.x + threadIdx.x; idx < total;
         idx += (long)gridDim.x * blockDim.x) {
        long r = idx / wp;
        int c = (int)(idx - r * wp);
        float v = (c < w) ? in[r * (long)w + c] : 0.f;
        wsplit16(hi, lo, idx, v);
    }
}

// fp32 -> 1x fp16 (weights, same layout)
__global__ void split1h_kernel(const float* __restrict__ in,
                               __half* __restrict__ out, long total)
{
    for (long idx = (long)blockIdx.x * blockDim.x + threadIdx.x; idx < total;
         idx += (long)gridDim.x * blockDim.x)
        out[idx] = __float2half_rn(in[idx]);
}

// transpose + single fp16 (weights): W[K][N] -> Wt[N][Kp]
__global__ void tsplit1h_kernel(const float* __restrict__ W,
                                __half* __restrict__ out,
                                int K, int N, int Kp)
{
    __shared__ float t[32][33];
    int k0 = blockIdx.x * 32, n0 = blockIdx.y * 32;
    for (int i = threadIdx.y; i < 32; i += 8) {
        int k = k0 + i, n = n0 + threadIdx.x;
        t[i][threadIdx.x] = (k < K && n < N) ? W[(size_t)k * N + n] : 0.f;
    }
    __syncthreads();
    for (int i = threadIdx.y; i < 32; i += 8) {
        int n = n0 + i, k = k0 + threadIdx.x;
        out[(size_t)n * Kp + k] = __float2half_rn(t[threadIdx.x][i]);
    }
}

// ---------------- LayerNorm fused with fp16 split+pad --------------------------
__global__ __launch_bounds__(256) void ln_split_kernel(
    const float* __restrict__ in, const float* __restrict__ w, const float* __restrict__ bb,
    __half* __restrict__ hi, __half* __restrict__ lo,
    int width, int inStride, int wp)
{
    int row = blockIdx.x;
    const float* x = in + (size_t)row * inStride;
    float s = 0.f, s2 = 0.f;
    for (int i = threadIdx.x; i < width; i += 256) { float v = x[i]; s += v; s2 += v * v; }
    __shared__ float sh[64];
#pragma unroll
    for (int o = 16; o > 0; o >>= 1) {
        s  += __shfl_down_sync(0xffffffffu, s,  o);
        s2 += __shfl_down_sync(0xffffffffu, s2, o);
    }
    int wid = threadIdx.x >> 5, lid = threadIdx.x & 31;
    if (lid == 0) { sh[wid] = s; sh[32 + wid] = s2; }
    __syncthreads();
    if (threadIdx.x == 0) {
        float ts = 0.f, ts2 = 0.f;
        for (int i = 0; i < 8; i++) { ts += sh[i]; ts2 += sh[32 + i]; }
        sh[0] = ts; sh[32] = ts2;
    }
    __syncthreads();
    float mean = sh[0] / width;
    float var = sh[32] / width - mean * mean;
    float inv = rsqrtf(var + 1e-5f);
    for (int i = threadIdx.x; i < wp; i += 256) {
        float y = 0.f;
        if (i < width) y = (x[i] - mean) * inv * w[i] + bb[i];
        wsplit16(hi, lo, (size_t)row * wp + i, y);
    }
}

// ---------------- RoPE + split prep kernels (attention side: bf16) -------------
__device__ __forceinline__ void rope_cs(int s, int j, float& c, float& sn) {
    float fr = powf(10000.f, -(float)(2 * j) / 128.f);
    float ang = (float)s * fr;
    sn = sinf(ang); c = cosf(ang);
}
__device__ __forceinline__ void wsplitb(__nv_bfloat16* hi, __nv_bfloat16* lo, size_t o, float v) {
    __nv_bfloat16 h = __float2bfloat16(v);
    hi[o] = h;
    lo[o] = __float2bfloat16(v - __bfloat162float(h));
}

__global__ void qprep_kernel(const float* __restrict__ Qf,
                             __nv_bfloat16* __restrict__ hi, __nv_bfloat16* __restrict__ lo)
{
    int row = blockIdx.x, h = blockIdx.y, j = threadIdx.x;  // 64 threads
    int s = row & (Sseq - 1);
    size_t base = (size_t)row * Dm + h * DHd;
    wsplitb(hi, lo, base + j, Qf[base + j]);
    if (j < 32) {
        float c, sn; rope_cs(s, j, c, sn);
        float x1 = Qf[base + 64 + j], x2 = Qf[base + 96 + j];
        wsplitb(hi, lo, base + 64 + j, x1 * c - x2 * sn);
        wsplitb(hi, lo, base + 96 + j, x2 * c + x1 * sn);
    }
}

__global__ void kprep_kernel(const float* __restrict__ KVf, const float* __restrict__ ckv,
                             __nv_bfloat16* __restrict__ hi, __nv_bfloat16* __restrict__ lo)
{
    int row = blockIdx.x, h = blockIdx.y, j = threadIdx.x;  // 64 threads
    int s = row & (Sseq - 1);
    size_t ob = (size_t)row * Dm + h * DHd;
    wsplitb(hi, lo, ob + j, KVf[(size_t)row * KVUP_W + h * 192 + j]);
    if (j < 32) {
        float c, sn; rope_cs(s, j, c, sn);
        const float* src = ckv + (size_t)row * CKV_W + KVP;
        float x1 = src[j], x2 = src[j + 32];
        wsplitb(hi, lo, ob + 64 + j, x1 * c - x2 * sn);
        wsplitb(hi, lo, ob + 96 + j, x2 * c + x1 * sn);
    }
}

__global__ void vprep_kernel(const float* __restrict__ KVf,
                             __nv_bfloat16* __restrict__ hi, __nv_bfloat16* __restrict__ lo)
{
    int row = blockIdx.x, h = blockIdx.y, d = threadIdx.x;  // 128 threads
    wsplitb(hi, lo, (size_t)row * Dm + h * DHd + d, KVf[(size_t)row * KVUP_W + h * 192 + 64 + d]);
}

// ---------------- HMMA flash attention (bf16 3-term; fp16 hi/lo output) --------
#define AQ_H 0
#define AQ_L 20480
#define AKV  40960
#define KV_STRIDE 75776
#define A_SS 192512
#define A_PH 209920
#define A_PL 219136
#define A_M  228352
#define A_L  228608
#define A_A  228864
#define ATT_SMEM 229120

__global__ __launch_bounds__(256) void attn_hmma(
    const __nv_bfloat16* __restrict__ Qh, const __nv_bfloat16* __restrict__ Ql,
    const __nv_bfloat16* __restrict__ Kh, const __nv_bfloat16* __restrict__ Kl,
    const __nv_bfloat16* __restrict__ Vh, const __nv_bfloat16* __restrict__ Vl,
    __half* __restrict__ Oh, __half* __restrict__ Ol)
{
    extern __shared__ char sm[];
    const uint32_t sb = smem_u32(sm);
    float* mrow = (float*)(sm + A_M);
    float* lrow = (float*)(sm + A_L);
    float* arow = (float*)(sm + A_A);
    float* Ss   = (float*)(sm + A_SS);

    const int qt = blockIdx.x, h = blockIdx.y, b = blockIdx.z;
    const int q0 = qt * 64;
    const int tid = threadIdx.x, lane = tid & 31, wid = tid >> 5;
    const int wm = wid >> 1, wn = wid & 1;
    const float scale = 0.08838834764831845f;

    {
        const __nv_bfloat16* g0[2] = { Qh, Ql };
#pragma unroll
        for (int part = 0; part < 2; part++) {
            const uint32_t base = sb + AQ_H + part * 20480;
#pragma unroll
            for (int i = 0; i < 4; i++) {
                int idx = tid + i * 256;
                int r = idx >> 4, s = idx & 15;
                uint32_t sa = base + (s >> 2) * 5120 + r * 80 + (s & 3) * 16;
                const __nv_bfloat16* g = g0[part] + (size_t)(b * Sseq + q0 + r) * Dm + h * DHd + s * 8;
                CP_ASYNC16(sa, g);
            }
        }
    }

    const __nv_bfloat16* gk[2] = { Kh, Kl };
    const __nv_bfloat16* gv[2] = { Vh, Vl };
    auto issue_kv = [&](int kt) {
        const int k0 = kt * 64;
        const uint32_t stg = sb + AKV + (uint32_t)(kt & 1) * KV_STRIDE;
#pragma unroll
        for (int part = 0; part < 2; part++) {
            const uint32_t kb = stg + part * 20480;
            const uint32_t vb = stg + 40960 + part * 17408;
#pragma unroll
            for (int i = 0; i < 4; i++) {
                int idx = tid + i * 256;
                int r = idx >> 4, s = idx & 15;
                size_t grow = (size_t)(b * Sseq + k0 + r) * Dm + h * DHd + s * 8;
                CP_ASYNC16(kb + (s >> 2) * 5120 + r * 80 + (s & 3) * 16, gk[part] + grow);
                CP_ASYNC16(vb + r * 272 + s * 16, gv[part] + grow);
            }
        }
        CP_COMMIT();
    };

    if (tid < 64) { mrow[tid] = -INFINITY; lrow[tid] = 0.f; }

    float o[8][4];
#pragma unroll
    for (int i = 0; i < 8; i++)
#pragma unroll
        for (int j = 0; j < 4; j++) o[i][j] = 0.f;

    const int nkt = qt + 1;
    issue_kv(0);

    for (int kt = 0; kt < nkt; kt++) {
        const int k0 = kt * 64;
        if (kt + 1 < nkt) { issue_kv(kt + 1); CP_WAIT(1); }
        else              { CP_WAIT(0); }
        __syncthreads();

        const uint32_t stg = sb + AKV + (uint32_t)(kt & 1) * KV_STRIDE;
        const uint32_t sKh = stg, sKl = stg + 20480;
        const uint32_t sVh = stg + 40960, sVl = stg + 58368;

        float s4[4][4];
#pragma unroll
        for (int i = 0; i < 4; i++)
#pragma unroll
            for (int j = 0; j < 4; j++) s4[i][j] = 0.f;

#pragma unroll
        for (int ks = 0; ks < 8; ks++) {
            uint32_t ah[4], al[4], bh[4][2], bl[4][2];
            const int chunk = ks >> 1;
            const uint32_t aoff = (uint32_t)(wm * 16 + (lane & 15)) * 80 +
                                  ((ks & 1) * 16 + ((lane >> 4) << 3)) * 2;
            LDSM_X4(ah, sb + AQ_H + chunk * 5120 + aoff);
            LDSM_X4(al, sb + AQ_L + chunk * 5120 + aoff);
#pragma unroll
            for (int nf = 0; nf < 4; nf++) {
                const uint32_t boff = (uint32_t)(wn * 32 + nf * 8 + (lane & 7)) * 80 +
                                      ((ks & 1) * 16 + (((lane >> 3) & 1) << 3)) * 2;
                LDSM_X2(bh[nf], sKh + chunk * 5120 + boff);
                LDSM_X2(bl[nf], sKl + chunk * 5120 + boff);
            }
#pragma unroll
            for (int nf = 0; nf < 4; nf++) MMA_BF16(s4[nf], ah, bh[nf][0], bh[nf][1]);
#pragma unroll
            for (int nf = 0; nf < 4; nf++) MMA_BF16(s4[nf], ah, bl[nf][0], bl[nf][1]);
#pragma unroll
            for (int nf = 0; nf < 4; nf++) MMA_BF16(s4[nf], al, bh[nf][0], bh[nf][1]);
        }
        {
            const int r0 = wm * 16 + (lane >> 2);
#pragma unroll
            for (int nf = 0; nf < 4; nf++) {
                const int c0 = wn * 32 + nf * 8 + (lane & 3) * 2;
#pragma unroll
                for (int e = 0; e < 4; e++) {
                    int r = r0 + (e >> 1) * 8;
                    int c = c0 + (e & 1);
                    float v = (k0 + c <= q0 + r) ? s4[nf][e] * scale : -INFINITY;
                    Ss[r * 68 + c] = v;
                }
            }
        }
        __syncthreads();

        {
            const int r = tid >> 2, cs = (tid & 3) * 16;
            float mx = -INFINITY;
#pragma unroll
            for (int j = 0; j < 16; j++) mx = fmaxf(mx, Ss[r * 68 + cs + j]);
            mx = fmaxf(mx, __shfl_xor_sync(0xffffffffu, mx, 1));
            mx = fmaxf(mx, __shfl_xor_sync(0xffffffffu, mx, 2));
            float mold = mrow[r];
            float mnew = fmaxf(mold, mx);
            float sum = 0.f;
            __nv_bfloat16* Ph = (__nv_bfloat16*)(sm + A_PH);
            __nv_bfloat16* Pl = (__nv_bfloat16*)(sm + A_PL);
#pragma unroll
            for (int j = 0; j < 16; j++) {
                float p = __expf(Ss[r * 68 + cs + j] - mnew);
                sum += p;
                __nv_bfloat16 ph = __float2bfloat16(p);
                Ph[r * 72 + cs + j] = ph;
                Pl[r * 72 + cs + j] = __float2bfloat16(p - __bfloat162float(ph));
            }
            sum += __shfl_xor_sync(0xffffffffu, sum, 1);
            sum += __shfl_xor_sync(0xffffffffu, sum, 2);
            if ((tid & 3) == 0) {
                float alpha = __expf(mold - mnew);
                arow[r] = alpha;
                lrow[r] = lrow[r] * alpha + sum;
                mrow[r] = mnew;
            }
        }
        __syncthreads();

        {
            float al0 = arow[wm * 16 + (lane >> 2)];
            float al1 = arow[wm * 16 + (lane >> 2) + 8];
#pragma unroll
            for (int nf = 0; nf < 8; nf++) {
                o[nf][0] *= al0; o[nf][1] *= al0;
                o[nf][2] *= al1; o[nf][3] *= al1;
            }
        }

#pragma unroll
        for (int ks = 0; ks < 4; ks++) {
            uint32_t ah[4], al[4], bh[8][2], bl[8][2];
            const uint32_t aoff = (uint32_t)(wm * 16 + (lane & 15)) * 144 +
                                  (ks * 16 + ((lane >> 4) << 3)) * 2;
            LDSM_X4(ah, sb + A_PH + aoff);
            LDSM_X4(al, sb + A_PL + aoff);
            const int vrow = ks * 16 + (lane & 7) + ((lane >> 3) & 1) * 8;
#pragma unroll
            for (int nf = 0; nf < 8; nf++) {
                const uint32_t boff = (uint32_t)vrow * 272 + (wn * 64 + nf * 8) * 2;
                LDSM_X2_T(bh[nf], sVh + boff);
                LDSM_X2_T(bl[nf], sVl + boff);
            }
#pragma unroll
            for (int nf = 0; nf < 8; nf++) MMA_BF16(o[nf], ah, bh[nf][0], bh[nf][1]);
#pragma unroll
            for (int nf = 0; nf < 8; nf++) MMA_BF16(o[nf], ah, bl[nf][0], bl[nf][1]);
#pragma unroll
            for (int nf = 0; nf < 8; nf++) MMA_BF16(o[nf], al, bh[nf][0], bh[nf][1]);
        }
        __syncthreads();
    }

    {
        const int r0 = wm * 16 + (lane >> 2);
        const float inv0 = 1.f / lrow[r0];
        const float inv1 = 1.f / lrow[r0 + 8];
#pragma unroll
        for (int nf = 0; nf < 8; nf++) {
            const int c = wn * 64 + nf * 8 + (lane & 3) * 2;
            size_t g0 = (size_t)(b * Sseq + q0 + r0) * Dm + h * DHd + c;
            size_t g1 = (size_t)(b * Sseq + q0 + r0 + 8) * Dm + h * DHd + c;
            wsplit16(Oh, Ol, g0,     o[nf][0] * inv0);
            wsplit16(Oh, Ol, g0 + 1, o[nf][1] * inv0);
            wsplit16(Oh, Ol, g1,     o[nf][2] * inv1);
            wsplit16(Oh, Ol, g1 + 1, o[nf][3] * inv1);
        }
    }
}

// ---------------- host launcher -------------------------------------------------
extern "C" void kernel_launch(void* const* d_in, const int* in_sizes, int n_in,
                              void* d_out, int out_size)
{
    const float* query   = (const float*)d_in[0];
    const float* W_dq    = (const float*)d_in[1];
    const float* W_uq    = (const float*)d_in[2];
    const float* q_ln_w  = (const float*)d_in[3];
    const float* q_ln_b  = (const float*)d_in[4];
    const float* W_dkv   = (const float*)d_in[5];
    const float* W_ukv   = (const float*)d_in[6];
    const float* kv_ln_w = (const float*)d_in[7];
    const float* kv_ln_b = (const float*)d_in[8];
    const float* W_o     = (const float*)d_in[9];

    float* out = (float*)d_out;
    float* ckv = out + (size_t)ROWS * Dm;

    __half *qh, *ql, *cqh, *cql, *kvh, *kvl, *aoh, *aol;
    __half *wdq, *wuq, *wdkv, *wukv, *wo;
    __nv_bfloat16 *Qhb, *Qlb, *Khb, *Klb, *Vhb, *Vlb;
    float *cq, *Qf, *KVf;
    cudaGetSymbolAddress((void**)&qh, g_qh16);     cudaGetSymbolAddress((void**)&ql, g_ql16);
    cudaGetSymbolAddress((void**)&cq, g_cq);
    cudaGetSymbolAddress((void**)&cqh, g_cqh16);   cudaGetSymbolAddress((void**)&cql, g_cql16);
    cudaGetSymbolAddress((void**)&Qf, g_Q);
    cudaGetSymbolAddress((void**)&kvh, g_kvh16);   cudaGetSymbolAddress((void**)&kvl, g_kvl16);
    cudaGetSymbolAddress((void**)&KVf, g_KV);
    cudaGetSymbolAddress((void**)&aoh, g_aoh16);   cudaGetSymbolAddress((void**)&aol, g_aol16);
    cudaGetSymbolAddress((void**)&Qhb, g_Qhb);     cudaGetSymbolAddress((void**)&Qlb, g_Qlb);
    cudaGetSymbolAddress((void**)&Khb, g_Khb);     cudaGetSymbolAddress((void**)&Klb, g_Klb);
    cudaGetSymbolAddress((void**)&Vhb, g_Vhb);     cudaGetSymbolAddress((void**)&Vlb, g_Vlb);
    cudaGetSymbolAddress((void**)&wdq, g_wdq16);   cudaGetSymbolAddress((void**)&wuq, g_wuq16);
    cudaGetSymbolAddress((void**)&wdkv, g_wdkv16); cudaGetSymbolAddress((void**)&wukv, g_wukv16);
    cudaGetSymbolAddress((void**)&wo, g_wo16);

    cudaFuncSetAttribute(hmma_gemm, cudaFuncAttributeMaxDynamicSharedMemorySize, GEMM_SMEM);
    cudaFuncSetAttribute(attn_hmma, cudaFuncAttributeMaxDynamicSharedMemorySize, ATT_SMEM);

    static cudaStream_t s2 = 0;
    static cudaEvent_t evFork = 0, evJoin = 0;
    if (s2 == 0) {
        cudaStreamCreateWithFlags(&s2, cudaStreamNonBlocking);
        cudaEventCreateWithFlags(&evFork, cudaEventDisableTiming);
        cudaEventCreateWithFlags(&evJoin, cudaEventDisableTiming);
    }

    // ---- stream 0 (legacy): q path. launch index 3 = hmma_gemm (ncu target)
    {
        long tq = (long)ROWS * Dm;
        split2h_kernel<<<(int)((tq + 255) / 256), 256>>>(query, qh, ql, tq, Dm, Dm);  // 0
    }
    cudaEventRecord(evFork, 0);
    tsplit1h_kernel<<<dim3(Dm / 32, QP / 32), dim3(32, 8)>>>(W_dq, wdq, Dm, QP, Dm);   // 1
    tsplit1h_kernel<<<dim3(QP / 32, Dm / 32), dim3(32, 8)>>>(W_uq, wuq, QP, Dm, QP);   // 2
    hmma_gemm<<<dim3(QP / 128, ROWS / 128), 256, GEMM_SMEM>>>(qh, ql, wdq, cq, Dm, QP, QP); // 3 <- ncu
    ln_split_kernel<<<ROWS, 256>>>(cq, q_ln_w, q_ln_b, cqh, cql, QP, QP, QP);
    hmma_gemm<<<dim3(Dm / 128, ROWS / 128), 256, GEMM_SMEM>>>(cqh, cql, wuq, Qf, QP, Dm, Dm);
    qprep_kernel<<<dim3(ROWS, Hh), 64, 0>>>(Qf, Qhb, Qlb);

    // ---- stream s2: kv path (depends only on qh/ql via evFork)
    cudaStreamWaitEvent(s2, evFork, 0);
    tsplit1h_kernel<<<dim3(Dm / 32, CKV_NPAD / 32), dim3(32, 8), 0, s2>>>(W_dkv, wdkv, Dm, CKV_W, Dm);
    hmma_gemm<<<dim3(CKV_NPAD / 128, ROWS / 128), 256, GEMM_SMEM, s2>>>(qh, ql, wdkv, ckv, Dm, CKV_W, CKV_W);
    ln_split_kernel<<<ROWS, 256, 0, s2>>>(ckv, kv_ln_w, kv_ln_b, kvh, kvl, KVP, CKV_W, KVP_PAD);
    tsplit1h_kernel<<<dim3(KVP_PAD / 32, KVUP_W / 32), dim3(32, 8), 0, s2>>>(W_ukv, wukv, KVP, KVUP_W, KVP_PAD);
    hmma_gemm<<<dim3(KVUP_W / 128, ROWS / 128), 256, GEMM_SMEM, s2>>>(kvh, kvl, wukv, KVf, KVP_PAD, KVUP_W, KVUP_W);
    kprep_kernel<<<dim3(ROWS, Hh), 64, 0, s2>>>(KVf, ckv, Khb, Klb);
    vprep_kernel<<<dim3(ROWS, Hh), 128, 0, s2>>>(KVf, Vhb, Vlb);
    {
        long tw = (long)Dm * Dm;
        split1h_kernel<<<(int)((tw + 255) / 256), 256, 0, s2>>>(W_o, wo, tw);
    }
    cudaEventRecord(evJoin, s2);

    // ---- join on stream 0: attention + output projection
    cudaStreamWaitEvent(0, evJoin, 0);
    attn_hmma<<<dim3(Sseq / 64, Hh, Bsz), 256, ATT_SMEM>>>(Qhb, Qlb, Khb, Klb, Vhb, Vlb, aoh, aol);
    hmma_gemm<<<dim3(Dm / 128, ROWS / 128), 256, GEMM_SMEM>>>(aoh, aol, wo, out, Dm, Dm, Dm);
}

// round 15
// speedup vs baseline: 1.3142x; 1.0967x over previous
#include <cuda_runtime.h>
#include <cuda_bf16.h>
#include <cuda_fp16.h>
#include <math.h>
#include <stdint.h>

#define Bsz 2
#define Sseq 2048
#define Dm 2048
#define Hh 16
#define DHd 128
#define QP 1024
#define KVP 1365
#define ROPE 64
#define CKV_W (KVP + ROPE)    // 1429
#define KVUP_W (Dm + Hh * 64) // 3072
#define ROWS (Bsz * Sseq)     // 4096
#define KVP_PAD 1408
#define CKV_NPAD 1536

// ---------------- scratch (device globals; no allocations) ------------------
__device__ __align__(256) __half g_qh16 [(size_t)ROWS * Dm];
__device__ __align__(256) __half g_ql16 [(size_t)ROWS * Dm];
__device__ __align__(256) float  g_cq   [(size_t)ROWS * QP];
__device__ __align__(256) __half g_cqh16[(size_t)ROWS * QP];
__device__ __align__(256) __half g_cql16[(size_t)ROWS * QP];
__device__ __align__(256) float  g_Q    [(size_t)ROWS * Dm];
__device__ __align__(256) __half g_kvh16[(size_t)ROWS * KVP_PAD];
__device__ __align__(256) __half g_kvl16[(size_t)ROWS * KVP_PAD];
__device__ __align__(256) float  g_KV   [(size_t)ROWS * KVUP_W];
__device__ __align__(256) __half g_aoh16[(size_t)ROWS * Dm];
__device__ __align__(256) __half g_aol16[(size_t)ROWS * Dm];
// attention operand buffers (fp16; Q hi/lo, K and V single), [row][h*128+d]
__device__ __align__(256) __half g_Qhb[(size_t)ROWS * Dm];
__device__ __align__(256) __half g_Qlb[(size_t)ROWS * Dm];
__device__ __align__(256) __half g_K16[(size_t)ROWS * Dm];
__device__ __align__(256) __half g_V16[(size_t)ROWS * Dm];
// weights: single fp16, transposed [N][Kp]
__device__ __align__(256) __half g_wdq16 [(size_t)QP * Dm];
__device__ __align__(256) __half g_wuq16 [(size_t)Dm * QP];
__device__ __align__(256) __half g_wdkv16[(size_t)CKV_NPAD * Dm];
__device__ __align__(256) __half g_wukv16[(size_t)KVUP_W * KVP_PAD];
__device__ __align__(256) __half g_wo16  [(size_t)Dm * Dm];

// ---------------- PTX helpers -------------------------------------------------
__device__ __forceinline__ uint32_t smem_u32(const void* p) {
    uint32_t a;
    asm("{ .reg .u64 t; cvta.to.shared.u64 t, %1; cvt.u32.u64 %0, t; }" : "=r"(a) : "l"(p));
    return a;
}
#define LDSM_X4(r, ad) \
    asm volatile("ldmatrix.sync.aligned.m8n8.x4.shared.b16 {%0,%1,%2,%3}, [%4];" \
        : "=r"((r)[0]), "=r"((r)[1]), "=r"((r)[2]), "=r"((r)[3]) : "r"(ad))
#define LDSM_X2(r, ad) \
    asm volatile("ldmatrix.sync.aligned.m8n8.x2.shared.b16 {%0,%1}, [%2];" \
        : "=r"((r)[0]), "=r"((r)[1]) : "r"(ad))
#define LDSM_X2_T(r, ad) \
    asm volatile("ldmatrix.sync.aligned.m8n8.x2.trans.shared.b16 {%0,%1}, [%2];" \
        : "=r"((r)[0]), "=r"((r)[1]) : "r"(ad))
#define MMA_F16(d, a, b0, b1) \
    asm volatile("mma.sync.aligned.m16n8k16.row.col.f32.f16.f16.f32 " \
        "{%0,%1,%2,%3},{%4,%5,%6,%7},{%8,%9},{%0,%1,%2,%3};" \
        : "+f"((d)[0]), "+f"((d)[1]), "+f"((d)[2]), "+f"((d)[3]) \
        : "r"((a)[0]), "r"((a)[1]), "r"((a)[2]), "r"((a)[3]), "r"(b0), "r"(b1))
#define CP_ASYNC16(sa, ga) \
    asm volatile("cp.async.cg.shared.global [%0], [%1], 16;" :: "r"(sa), "l"(ga))
#define CP_COMMIT() asm volatile("cp.async.commit_group;" ::: "memory")
#define CP_WAIT(n)  asm volatile("cp.async.wait_group %0;" :: "n"(n) : "memory")

// ---------------- HMMA fp16 GEMM: A = Ah+Al (2x fp16), B = 1x fp16 -------------
#define TILE_BYTES 18432          // 128 rows * 144B (64 halves + 16B pad)
#define STG_BYTES  (3 * TILE_BYTES)
#define GEMM_SMEM  (2 * STG_BYTES)   // 110592

__global__ __launch_bounds__(256) void hmma_gemm(
    const __half* __restrict__ Ahi, const __half* __restrict__ Alo,
    const __half* __restrict__ B,
    float* __restrict__ C, int Kp, int Nreal, int ldc)
{
    extern __shared__ char smm[];
    const uint32_t sbase = smem_u32(smm);
    const int tid = threadIdx.x, lane = tid & 31, wid = tid >> 5;
    const int m0 = blockIdx.y * 128, n0 = blockIdx.x * 128;
    const int wm = wid >> 2, wn = wid & 3;
    const __half* srcs[3] = { Ahi, Alo, B };

    float acc[4][4][4];
#pragma unroll
    for (int i = 0; i < 4; i++)
#pragma unroll
        for (int j = 0; j < 4; j++)
#pragma unroll
            for (int q = 0; q < 4; q++) acc[i][j][q] = 0.f;

    const int nch = Kp >> 6;

    auto issue = [&](int c) {
        const int s = c & 1;
        const int k0 = c << 6;
#pragma unroll
        for (int t = 0; t < 3; t++) {
            const int row0 = (t < 2) ? m0 : n0;
            const uint32_t sb = sbase + (uint32_t)s * STG_BYTES + (uint32_t)t * TILE_BYTES;
#pragma unroll
            for (int it = 0; it < 4; it++) {
                const int idx = tid + it * 256;
                const int r = idx >> 3, seg = idx & 7;
                CP_ASYNC16(sb + r * 144 + seg * 16,
                           srcs[t] + (size_t)(row0 + r) * Kp + k0 + seg * 8);
            }
        }
        CP_COMMIT();
    };

    issue(0);

    const int a_row = wm * 64 + (lane & 15);
    const int a_colh = (lane >> 4) << 3;
    const int b_row = wn * 32 + (lane & 7);
    const int b_colh = (((lane >> 3) & 1) << 3);

    for (int c = 0; c < nch; c++) {
        const int s = c & 1;
        if (c + 1 < nch) { issue(c + 1); CP_WAIT(1); }
        else             { CP_WAIT(0); }
        __syncthreads();

        const uint32_t sAh = sbase + (uint32_t)s * STG_BYTES;
        const uint32_t sAl = sAh + TILE_BYTES;
        const uint32_t sB  = sAh + 2 * TILE_BYTES;

#pragma unroll
        for (int ks = 0; ks < 4; ks++) {
            uint32_t ah[4][4], al[4][4], bb[4][2];
            const int acol = ks * 16 + a_colh;
#pragma unroll
            for (int mi = 0; mi < 4; mi++) {
                const uint32_t off = (uint32_t)(a_row + mi * 16) * 144 + acol * 2;
                LDSM_X4(ah[mi], sAh + off);
                LDSM_X4(al[mi], sAl + off);
            }
            const int bcol = ks * 16 + b_colh;
#pragma unroll
            for (int ni = 0; ni < 4; ni++) {
                const uint32_t off = (uint32_t)(b_row + ni * 8) * 144 + bcol * 2;
                LDSM_X2(bb[ni], sB + off);
            }
#pragma unroll
            for (int mi = 0; mi < 4; mi++)
#pragma unroll
                for (int ni = 0; ni < 4; ni++)
                    MMA_F16(acc[mi][ni], ah[mi], bb[ni][0], bb[ni][1]);
#pragma unroll
            for (int mi = 0; mi < 4; mi++)
#pragma unroll
                for (int ni = 0; ni < 4; ni++)
                    MMA_F16(acc[mi][ni], al[mi], bb[ni][0], bb[ni][1]);
        }
        __syncthreads();
    }

#pragma unroll
    for (int mi = 0; mi < 4; mi++) {
        const int row = m0 + wm * 64 + mi * 16 + (lane >> 2);
#pragma unroll
        for (int ni = 0; ni < 4; ni++) {
            const int col = n0 + wn * 32 + ni * 8 + (lane & 3) * 2;
            float* p0 = C + (size_t)row * ldc + col;
            float* p1 = C + (size_t)(row + 8) * ldc + col;
            if (col < Nreal)     { p0[0] = acc[mi][ni][0]; p1[0] = acc[mi][ni][2]; }
            if (col + 1 < Nreal) { p0[1] = acc[mi][ni][1]; p1[1] = acc[mi][ni][3]; }
        }
    }
}

// ---------------- split / transpose-split kernels -----------------------------
__device__ __forceinline__ void wsplit16(__half* hi, __half* lo, size_t o, float v) {
    __half h = __float2half_rn(v);
    hi[o] = h;
    lo[o] = __float2half_rn(v - __half2float(h));
}

__global__ void split2h_kernel(const float* __restrict__ in,
                               __half* __restrict__ hi, __half* __restrict__ lo,
                               long total, int w, int wp)
{
    for (long idx = (long)blockIdx.x * blockDim.x + threadIdx.x; idx < total;
         idx += (long)gridDim.x * blockDim.x) {
        long r = idx / wp;
        int c = (int)(idx - r * wp);
        float v = (c < w) ? in[r * (long)w + c] : 0.f;
        wsplit16(hi, lo, idx, v);
    }
}

__global__ void split1h_kernel(const float* __restrict__ in,
                               __half* __restrict__ out, long total)
{
    for (long idx = (long)blockIdx.x * blockDim.x + threadIdx.x; idx < total;
         idx += (long)gridDim.x * blockDim.x)
        out[idx] = __float2half_rn(in[idx]);
}

__global__ void tsplit1h_kernel(const float* __restrict__ W,
                                __half* __restrict__ out,
                                int K, int N, int Kp)
{
    __shared__ float t[32][33];
    int k0 = blockIdx.x * 32, n0 = blockIdx.y * 32;
    for (int i = threadIdx.y; i < 32; i += 8) {
        int k = k0 + i, n = n0 + threadIdx.x;
        t[i][threadIdx.x] = (k < K && n < N) ? W[(size_t)k * N + n] : 0.f;
    }
    __syncthreads();
    for (int i = threadIdx.y; i < 32; i += 8) {
        int n = n0 + i, k = k0 + threadIdx.x;
        out[(size_t)n * Kp + k] = __float2half_rn(t[threadIdx.x][i]);
    }
}

// ---------------- LayerNorm fused with fp16 split+pad --------------------------
__global__ __launch_bounds__(256) void ln_split_kernel(
    const float* __restrict__ in, const float* __restrict__ w, const float* __restrict__ bb,
    __half* __restrict__ hi, __half* __restrict__ lo,
    int width, int inStride, int wp)
{
    int row = blockIdx.x;
    const float* x = in + (size_t)row * inStride;
    float s = 0.f, s2 = 0.f;
    for (int i = threadIdx.x; i < width; i += 256) { float v = x[i]; s += v; s2 += v * v; }
    __shared__ float sh[64];
#pragma unroll
    for (int o = 16; o > 0; o >>= 1) {
        s  += __shfl_down_sync(0xffffffffu, s,  o);
        s2 += __shfl_down_sync(0xffffffffu, s2, o);
    }
    int wid = threadIdx.x >> 5, lid = threadIdx.x & 31;
    if (lid == 0) { sh[wid] = s; sh[32 + wid] = s2; }
    __syncthreads();
    if (threadIdx.x == 0) {
        float ts = 0.f, ts2 = 0.f;
        for (int i = 0; i < 8; i++) { ts += sh[i]; ts2 += sh[32 + i]; }
        sh[0] = ts; sh[32] = ts2;
    }
    __syncthreads();
    float mean = sh[0] / width;
    float var = sh[32] / width - mean * mean;
    float inv = rsqrtf(var + 1e-5f);
    for (int i = threadIdx.x; i < wp; i += 256) {
        float y = 0.f;
        if (i < width) y = (x[i] - mean) * inv * w[i] + bb[i];
        wsplit16(hi, lo, (size_t)row * wp + i, y);
    }
}

// ---------------- RoPE + prep kernels (attention: Q 2xfp16, K/V 1xfp16) --------
__device__ __forceinline__ void rope_cs(int s, int j, float& c, float& sn) {
    float fr = powf(10000.f, -(float)(2 * j) / 128.f);
    float ang = (float)s * fr;
    sn = sinf(ang); c = cosf(ang);
}

__global__ void qprep_kernel(const float* __restrict__ Qf,
                             __half* __restrict__ hi, __half* __restrict__ lo)
{
    int row = blockIdx.x, h = blockIdx.y, j = threadIdx.x;  // 64 threads
    int s = row & (Sseq - 1);
    size_t base = (size_t)row * Dm + h * DHd;
    wsplit16(hi, lo, base + j, Qf[base + j]);
    if (j < 32) {
        float c, sn; rope_cs(s, j, c, sn);
        float x1 = Qf[base + 64 + j], x2 = Qf[base + 96 + j];
        wsplit16(hi, lo, base + 64 + j, x1 * c - x2 * sn);
        wsplit16(hi, lo, base + 96 + j, x2 * c + x1 * sn);
    }
}

__global__ void kprep_kernel(const float* __restrict__ KVf, const float* __restrict__ ckv,
                             __half* __restrict__ K16)
{
    int row = blockIdx.x, h = blockIdx.y, j = threadIdx.x;  // 64 threads
    int s = row & (Sseq - 1);
    size_t ob = (size_t)row * Dm + h * DHd;
    K16[ob + j] = __float2half_rn(KVf[(size_t)row * KVUP_W + h * 192 + j]);
    if (j < 32) {
        float c, sn; rope_cs(s, j, c, sn);
        const float* src = ckv + (size_t)row * CKV_W + KVP;
        float x1 = src[j], x2 = src[j + 32];
        K16[ob + 64 + j] = __float2half_rn(x1 * c - x2 * sn);
        K16[ob + 96 + j] = __float2half_rn(x2 * c + x1 * sn);
    }
}

__global__ void vprep_kernel(const float* __restrict__ KVf, __half* __restrict__ V16)
{
    int row = blockIdx.x, h = blockIdx.y, d = threadIdx.x;  // 128 threads
    V16[(size_t)row * Dm + h * DHd + d] =
        __float2half_rn(KVf[(size_t)row * KVUP_W + h * 192 + 64 + d]);
}

// ---------------- HMMA flash attention (fp16: Q 2-term, K/V 1-term) ------------
#define AQ_H 0
#define AQ_L 20480
#define AKV  40960
#define KV_STRIDE 37888           // K 20480 + V 17408 per stage
#define A_SS 116736
#define A_PH 134144
#define A_PL 143360
#define A_M  152576
#define A_L  152832
#define A_A  153088
#define ATT_SMEM 153344

__global__ __launch_bounds__(256) void attn_hmma(
    const __half* __restrict__ Qh, const __half* __restrict__ Ql,
    const __half* __restrict__ K16, const __half* __restrict__ V16,
    __half* __restrict__ Oh, __half* __restrict__ Ol)
{
    extern __shared__ char sm[];
    const uint32_t sb = smem_u32(sm);
    float* mrow = (float*)(sm + A_M);
    float* lrow = (float*)(sm + A_L);
    float* arow = (float*)(sm + A_A);
    float* Ss   = (float*)(sm + A_SS);

    const int qt = blockIdx.x, h = blockIdx.y, b = blockIdx.z;
    const int q0 = qt * 64;
    const int tid = threadIdx.x, lane = tid & 31, wid = tid >> 5;
    const int wm = wid >> 1, wn = wid & 1;
    const float scale = 0.08838834764831845f;

    {
        const __half* g0[2] = { Qh, Ql };
#pragma unroll
        for (int part = 0; part < 2; part++) {
            const uint32_t base = sb + AQ_H + part * 20480;
#pragma unroll
            for (int i = 0; i < 4; i++) {
                int idx = tid + i * 256;
                int r = idx >> 4, s = idx & 15;
                uint32_t sa = base + (s >> 2) * 5120 + r * 80 + (s & 3) * 16;
                const __half* g = g0[part] + (size_t)(b * Sseq + q0 + r) * Dm + h * DHd + s * 8;
                CP_ASYNC16(sa, g);
            }
        }
    }

    auto issue_kv = [&](int kt) {
        const int k0 = kt * 64;
        const uint32_t stg = sb + AKV + (uint32_t)(kt & 1) * KV_STRIDE;
        const uint32_t kb = stg, vb = stg + 20480;
#pragma unroll
        for (int i = 0; i < 4; i++) {
            int idx = tid + i * 256;
            int r = idx >> 4, s = idx & 15;
            size_t grow = (size_t)(b * Sseq + k0 + r) * Dm + h * DHd + s * 8;
            CP_ASYNC16(kb + (s >> 2) * 5120 + r * 80 + (s & 3) * 16, K16 + grow);
            CP_ASYNC16(vb + r * 272 + s * 16, V16 + grow);
        }
        CP_COMMIT();
    };

    if (tid < 64) { mrow[tid] = -INFINITY; lrow[tid] = 0.f; }

    float o[8][4];
#pragma unroll
    for (int i = 0; i < 8; i++)
#pragma unroll
        for (int j = 0; j < 4; j++) o[i][j] = 0.f;

    const int nkt = qt + 1;
    issue_kv(0);

    for (int kt = 0; kt < nkt; kt++) {
        const int k0 = kt * 64;
        if (kt + 1 < nkt) { issue_kv(kt + 1); CP_WAIT(1); }
        else              { CP_WAIT(0); }
        __syncthreads();

        const uint32_t stg = sb + AKV + (uint32_t)(kt & 1) * KV_STRIDE;
        const uint32_t sK = stg, sV = stg + 20480;

        float s4[4][4];
#pragma unroll
        for (int i = 0; i < 4; i++)
#pragma unroll
            for (int j = 0; j < 4; j++) s4[i][j] = 0.f;

#pragma unroll
        for (int ks = 0; ks < 8; ks++) {
            uint32_t ah[4], al[4], bb[4][2];
            const int chunk = ks >> 1;
            const uint32_t aoff = (uint32_t)(wm * 16 + (lane & 15)) * 80 +
                                  ((ks & 1) * 16 + ((lane >> 4) << 3)) * 2;
            LDSM_X4(ah, sb + AQ_H + chunk * 5120 + aoff);
            LDSM_X4(al, sb + AQ_L + chunk * 5120 + aoff);
#pragma unroll
            for (int nf = 0; nf < 4; nf++) {
                const uint32_t boff = (uint32_t)(wn * 32 + nf * 8 + (lane & 7)) * 80 +
                                      ((ks & 1) * 16 + (((lane >> 3) & 1) << 3)) * 2;
                LDSM_X2(bb[nf], sK + chunk * 5120 + boff);
            }
#pragma unroll
            for (int nf = 0; nf < 4; nf++) MMA_F16(s4[nf], ah, bb[nf][0], bb[nf][1]);
#pragma unroll
            for (int nf = 0; nf < 4; nf++) MMA_F16(s4[nf], al, bb[nf][0], bb[nf][1]);
        }
        {
            const int r0 = wm * 16 + (lane >> 2);
#pragma unroll
            for (int nf = 0; nf < 4; nf++) {
                const int c0 = wn * 32 + nf * 8 + (lane & 3) * 2;
#pragma unroll
                for (int e = 0; e < 4; e++) {
                    int r = r0 + (e >> 1) * 8;
                    int c = c0 + (e & 1);
                    float v = (k0 + c <= q0 + r) ? s4[nf][e] * scale : -INFINITY;
                    Ss[r * 68 + c] = v;
                }
            }
        }
        __syncthreads();

        {
            const int r = tid >> 2, cs = (tid & 3) * 16;
            float mx = -INFINITY;
#pragma unroll
            for (int j = 0; j < 16; j++) mx = fmaxf(mx, Ss[r * 68 + cs + j]);
            mx = fmaxf(mx, __shfl_xor_sync(0xffffffffu, mx, 1));
            mx = fmaxf(mx, __shfl_xor_sync(0xffffffffu, mx, 2));
            float mold = mrow[r];
            float mnew = fmaxf(mold, mx);
            float sum = 0.f;
            __half* Ph = (__half*)(sm + A_PH);
            __half* Pl = (__half*)(sm + A_PL);
#pragma unroll
            for (int j = 0; j < 16; j++) {
                float p = __expf(Ss[r * 68 + cs + j] - mnew);
                sum += p;
                __half ph = __float2half_rn(p);
                Ph[r * 72 + cs + j] = ph;
                Pl[r * 72 + cs + j] = __float2half_rn(p - __half2float(ph));
            }
            sum += __shfl_xor_sync(0xffffffffu, sum, 1);
            sum += __shfl_xor_sync(0xffffffffu, sum, 2);
            if ((tid & 3) == 0) {
                float alpha = __expf(mold - mnew);
                arow[r] = alpha;
                lrow[r] = lrow[r] * alpha + sum;
                mrow[r] = mnew;
            }
        }
        __syncthreads();

        {
            float al0 = arow[wm * 16 + (lane >> 2)];
            float al1 = arow[wm * 16 + (lane >> 2) + 8];
#pragma unroll
            for (int nf = 0; nf < 8; nf++) {
                o[nf][0] *= al0; o[nf][1] *= al0;
                o[nf][2] *= al1; o[nf][3] *= al1;
            }
        }

#pragma unroll
        for (int ks = 0; ks < 4; ks++) {
            uint32_t ah[4], al[4], bv[8][2];
            const uint32_t aoff = (uint32_t)(wm * 16 + (lane & 15)) * 144 +
                                  (ks * 16 + ((lane >> 4) << 3)) * 2;
            LDSM_X4(ah, sb + A_PH + aoff);
            LDSM_X4(al, sb + A_PL + aoff);
            const int vrow = ks * 16 + (lane & 7) + ((lane >> 3) & 1) * 8;
#pragma unroll
            for (int nf = 0; nf < 8; nf++) {
                const uint32_t boff = (uint32_t)vrow * 272 + (wn * 64 + nf * 8) * 2;
                LDSM_X2_T(bv[nf], sV + boff);
            }
#pragma unroll
            for (int nf = 0; nf < 8; nf++) MMA_F16(o[nf], ah, bv[nf][0], bv[nf][1]);
#pragma unroll
            for (int nf = 0; nf < 8; nf++) MMA_F16(o[nf], al, bv[nf][0], bv[nf][1]);
        }
        __syncthreads();
    }

    {
        const int r0 = wm * 16 + (lane >> 2);
        const float inv0 = 1.f / lrow[r0];
        const float inv1 = 1.f / lrow[r0 + 8];
#pragma unroll
        for (int nf = 0; nf < 8; nf++) {
            const int c = wn * 64 + nf * 8 + (lane & 3) * 2;
            size_t g0 = (size_t)(b * Sseq + q0 + r0) * Dm + h * DHd + c;
            size_t g1 = (size_t)(b * Sseq + q0 + r0 + 8) * Dm + h * DHd + c;
            wsplit16(Oh, Ol, g0,     o[nf][0] * inv0);
            wsplit16(Oh, Ol, g0 + 1, o[nf][1] * inv0);
            wsplit16(Oh, Ol, g1,     o[nf][2] * inv1);
            wsplit16(Oh, Ol, g1 + 1, o[nf][3] * inv1);
        }
    }
}

// ---------------- host launcher -------------------------------------------------
extern "C" void kernel_launch(void* const* d_in, const int* in_sizes, int n_in,
                              void* d_out, int out_size)
{
    const float* query   = (const float*)d_in[0];
    const float* W_dq    = (const float*)d_in[1];
    const float* W_uq    = (const float*)d_in[2];
    const float* q_ln_w  = (const float*)d_in[3];
    const float* q_ln_b  = (const float*)d_in[4];
    const float* W_dkv   = (const float*)d_in[5];
    const float* W_ukv   = (const float*)d_in[6];
    const float* kv_ln_w = (const float*)d_in[7];
    const float* kv_ln_b = (const float*)d_in[8];
    const float* W_o     = (const float*)d_in[9];

    float* out = (float*)d_out;
    float* ckv = out + (size_t)ROWS * Dm;

    __half *qh, *ql, *cqh, *cql, *kvh, *kvl, *aoh, *aol;
    __half *wdq, *wuq, *wdkv, *wukv, *wo;
    __half *Qhb, *Qlb, *K16, *V16;
    float *cq, *Qf, *KVf;
    cudaGetSymbolAddress((void**)&qh, g_qh16);     cudaGetSymbolAddress((void**)&ql, g_ql16);
    cudaGetSymbolAddress((void**)&cq, g_cq);
    cudaGetSymbolAddress((void**)&cqh, g_cqh16);   cudaGetSymbolAddress((void**)&cql, g_cql16);
    cudaGetSymbolAddress((void**)&Qf, g_Q);
    cudaGetSymbolAddress((void**)&kvh, g_kvh16);   cudaGetSymbolAddress((void**)&kvl, g_kvl16);
    cudaGetSymbolAddress((void**)&KVf, g_KV);
    cudaGetSymbolAddress((void**)&aoh, g_aoh16);   cudaGetSymbolAddress((void**)&aol, g_aol16);
    cudaGetSymbolAddress((void**)&Qhb, g_Qhb);     cudaGetSymbolAddress((void**)&Qlb, g_Qlb);
    cudaGetSymbolAddress((void**)&K16, g_K16);     cudaGetSymbolAddress((void**)&V16, g_V16);
    cudaGetSymbolAddress((void**)&wdq, g_wdq16);   cudaGetSymbolAddress((void**)&wuq, g_wuq16);
    cudaGetSymbolAddress((void**)&wdkv, g_wdkv16); cudaGetSymbolAddress((void**)&wukv, g_wukv16);
    cudaGetSymbolAddress((void**)&wo, g_wo16);

    cudaFuncSetAttribute(hmma_gemm, cudaFuncAttributeMaxDynamicSharedMemorySize, GEMM_SMEM);
    cudaFuncSetAttribute(attn_hmma, cudaFuncAttributeMaxDynamicSharedMemorySize, ATT_SMEM);

    static cudaStream_t s2 = 0;
    static cudaEvent_t evFork = 0, evJoin = 0;
    if (s2 == 0) {
        cudaStreamCreateWithFlags(&s2, cudaStreamNonBlocking);
        cudaEventCreateWithFlags(&evFork, cudaEventDisableTiming);
        cudaEventCreateWithFlags(&evJoin, cudaEventDisableTiming);
    }

    // ---- stream 0 (legacy): q path. launch index 3 = hmma_gemm (ncu target)
    {
        long tq = (long)ROWS * Dm;
        split2h_kernel<<<(int)((tq + 255) / 256), 256>>>(query, qh, ql, tq, Dm, Dm);  // 0
    }
    cudaEventRecord(evFork, 0);
    tsplit1h_kernel<<<dim3(Dm / 32, QP / 32), dim3(32, 8)>>>(W_dq, wdq, Dm, QP, Dm);   // 1
    tsplit1h_kernel<<<dim3(QP / 32, Dm / 32), dim3(32, 8)>>>(W_uq, wuq, QP, Dm, QP);   // 2
    hmma_gemm<<<dim3(QP / 128, ROWS / 128), 256, GEMM_SMEM>>>(qh, ql, wdq, cq, Dm, QP, QP); // 3 <- ncu
    ln_split_kernel<<<ROWS, 256>>>(cq, q_ln_w, q_ln_b, cqh, cql, QP, QP, QP);
    hmma_gemm<<<dim3(Dm / 128, ROWS / 128), 256, GEMM_SMEM>>>(cqh, cql, wuq, Qf, QP, Dm, Dm);
    qprep_kernel<<<dim3(ROWS, Hh), 64, 0>>>(Qf, Qhb, Qlb);

    // ---- stream s2: kv path (depends only on qh/ql via evFork)
    cudaStreamWaitEvent(s2, evFork, 0);
    tsplit1h_kernel<<<dim3(Dm / 32, CKV_NPAD / 32), dim3(32, 8), 0, s2>>>(W_dkv, wdkv, Dm, CKV_W, Dm);
    hmma_gemm<<<dim3(CKV_NPAD / 128, ROWS / 128), 256, GEMM_SMEM, s2>>>(qh, ql, wdkv, ckv, Dm, CKV_W, CKV_W);
    ln_split_kernel<<<ROWS, 256, 0, s2>>>(ckv, kv_ln_w, kv_ln_b, kvh, kvl, KVP, CKV_W, KVP_PAD);
    tsplit1h_kernel<<<dim3(KVP_PAD / 32, KVUP_W / 32), dim3(32, 8), 0, s2>>>(W_ukv, wukv, KVP, KVUP_W, KVP_PAD);
    hmma_gemm<<<dim3(KVUP_W / 128, ROWS / 128), 256, GEMM_SMEM, s2>>>(kvh, kvl, wukv, KVf, KVP_PAD, KVUP_W, KVUP_W);
    kprep_kernel<<<dim3(ROWS, Hh), 64, 0, s2>>>(KVf, ckv, K16);
    vprep_kernel<<<dim3(ROWS, Hh), 128, 0, s2>>>(KVf, V16);
    {
        long tw = (long)Dm * Dm;
        split1h_kernel<<<(int)((tw + 255) / 256), 256, 0, s2>>>(W_o, wo, tw);
    }
    cudaEventRecord(evJoin, s2);

    // ---- join on stream 0: attention + output projection
    cudaStreamWaitEvent(0, evJoin, 0);
    attn_hmma<<<dim3(Sseq / 64, Hh, Bsz), 256, ATT_SMEM>>>(Qhb, Qlb, K16, V16, aoh, aol);
    hmma_gemm<<<dim3(Dm / 128, ROWS / 128), 256, GEMM_SMEM>>>(aoh, aol, wo, out, Dm, Dm, Dm);
}

// round 16
// speedup vs baseline: 1.6771x; 1.2761x over previous
#include <cuda_runtime.h>
#include <cuda_fp16.h>
#include <math.h>
#include <stdint.h>

#define Bsz 2
#define Sseq 2048
#define Dm 2048
#define Hh 16
#define DHd 128
#define QP 1024
#define KVP 1365
#define ROPE 64
#define CKV_W (KVP + ROPE)    // 1429
#define KVUP_W (Dm + Hh * 64) // 3072
#define ROWS (Bsz * Sseq)     // 4096
#define KVP_PAD 1408
#define CKV_NPAD 1536

// ---------------- scratch (device globals; no allocations) ------------------
__device__ __align__(256) __half g_q16  [(size_t)ROWS * Dm];
__device__ __align__(256) float  g_cq   [(size_t)ROWS * QP];
__device__ __align__(256) __half g_cq16 [(size_t)ROWS * QP];
__device__ __align__(256) float  g_Q    [(size_t)ROWS * Dm];
__device__ __align__(256) __half g_kv16 [(size_t)ROWS * KVP_PAD];
__device__ __align__(256) float  g_KV   [(size_t)ROWS * KVUP_W];
__device__ __align__(256) __half g_ao16 [(size_t)ROWS * Dm];
// attention operand buffers (fp16; Q hi/lo, K and V single), [row][h*128+d]
__device__ __align__(256) __half g_Qhb[(size_t)ROWS * Dm];
__device__ __align__(256) __half g_Qlb[(size_t)ROWS * Dm];
__device__ __align__(256) __half g_K16[(size_t)ROWS * Dm];
__device__ __align__(256) __half g_V16[(size_t)ROWS * Dm];
// weights: single fp16, transposed [N][Kp]
__device__ __align__(256) __half g_wdq16 [(size_t)QP * Dm];
__device__ __align__(256) __half g_wuq16 [(size_t)Dm * QP];
__device__ __align__(256) __half g_wdkv16[(size_t)CKV_NPAD * Dm];
__device__ __align__(256) __half g_wukv16[(size_t)KVUP_W * KVP_PAD];
__device__ __align__(256) __half g_wo16  [(size_t)Dm * Dm];

// ---------------- PTX helpers -------------------------------------------------
__device__ __forceinline__ uint32_t smem_u32(const void* p) {
    uint32_t a;
    asm("{ .reg .u64 t; cvta.to.shared.u64 t, %1; cvt.u32.u64 %0, t; }" : "=r"(a) : "l"(p));
    return a;
}
#define LDSM_X4(r, ad) \
    asm volatile("ldmatrix.sync.aligned.m8n8.x4.shared.b16 {%0,%1,%2,%3}, [%4];" \
        : "=r"((r)[0]), "=r"((r)[1]), "=r"((r)[2]), "=r"((r)[3]) : "r"(ad))
#define LDSM_X2(r, ad) \
    asm volatile("ldmatrix.sync.aligned.m8n8.x2.shared.b16 {%0,%1}, [%2];" \
        : "=r"((r)[0]), "=r"((r)[1]) : "r"(ad))
#define LDSM_X2_T(r, ad) \
    asm volatile("ldmatrix.sync.aligned.m8n8.x2.trans.shared.b16 {%0,%1}, [%2];" \
        : "=r"((r)[0]), "=r"((r)[1]) : "r"(ad))
#define MMA_F16(d, a, b0, b1) \
    asm volatile("mma.sync.aligned.m16n8k16.row.col.f32.f16.f16.f32 " \
        "{%0,%1,%2,%3},{%4,%5,%6,%7},{%8,%9},{%0,%1,%2,%3};" \
        : "+f"((d)[0]), "+f"((d)[1]), "+f"((d)[2]), "+f"((d)[3]) \
        : "r"((a)[0]), "r"((a)[1]), "r"((a)[2]), "r"((a)[3]), "r"(b0), "r"(b1))
#define CP_ASYNC16(sa, ga) \
    asm volatile("cp.async.cg.shared.global [%0], [%1], 16;" :: "r"(sa), "l"(ga))
#define CP_COMMIT() asm volatile("cp.async.commit_group;" ::: "memory")
#define CP_WAIT(n)  asm volatile("cp.async.wait_group %0;" :: "n"(n) : "memory")

// ---------------- HMMA fp16 GEMM: A 1x fp16, B 1x fp16 -------------------------
// CTA 128x128, 8 warps (2M x 4N), warp tile 64x32, k-chunk 64, 2 stages.
#define TILE_BYTES 18432          // 128 rows * 144B (64 halves + 16B pad)
#define STG_BYTES  (2 * TILE_BYTES)
#define GEMM_SMEM  (2 * STG_BYTES)   // 73728

__global__ __launch_bounds__(256) void hmma_gemm(
    const __half* __restrict__ A, const __half* __restrict__ B,
    float* __restrict__ C, int Kp, int Nreal, int ldc)
{
    extern __shared__ char smm[];
    const uint32_t sbase = smem_u32(smm);
    const int tid = threadIdx.x, lane = tid & 31, wid = tid >> 5;
    const int m0 = blockIdx.y * 128, n0 = blockIdx.x * 128;
    const int wm = wid >> 2, wn = wid & 3;
    const __half* srcs[2] = { A, B };

    float acc[4][4][4];
#pragma unroll
    for (int i = 0; i < 4; i++)
#pragma unroll
        for (int j = 0; j < 4; j++)
#pragma unroll
            for (int q = 0; q < 4; q++) acc[i][j][q] = 0.f;

    const int nch = Kp >> 6;

    auto issue = [&](int c) {
        const int s = c & 1;
        const int k0 = c << 6;
#pragma unroll
        for (int t = 0; t < 2; t++) {
            const int row0 = (t == 0) ? m0 : n0;
            const uint32_t sb = sbase + (uint32_t)s * STG_BYTES + (uint32_t)t * TILE_BYTES;
#pragma unroll
            for (int it = 0; it < 4; it++) {
                const int idx = tid + it * 256;
                const int r = idx >> 3, seg = idx & 7;
                CP_ASYNC16(sb + r * 144 + seg * 16,
                           srcs[t] + (size_t)(row0 + r) * Kp + k0 + seg * 8);
            }
        }
        CP_COMMIT();
    };

    issue(0);

    const int a_row = wm * 64 + (lane & 15);
    const int a_colh = (lane >> 4) << 3;
    const int b_row = wn * 32 + (lane & 7);
    const int b_colh = (((lane >> 3) & 1) << 3);

    for (int c = 0; c < nch; c++) {
        const int s = c & 1;
        if (c + 1 < nch) { issue(c + 1); CP_WAIT(1); }
        else             { CP_WAIT(0); }
        __syncthreads();

        const uint32_t sA = sbase + (uint32_t)s * STG_BYTES;
        const uint32_t sB = sA + TILE_BYTES;

#pragma unroll
        for (int ks = 0; ks < 4; ks++) {
            uint32_t aa[4][4], bb[4][2];
            const int acol = ks * 16 + a_colh;
#pragma unroll
            for (int mi = 0; mi < 4; mi++) {
                const uint32_t off = (uint32_t)(a_row + mi * 16) * 144 + acol * 2;
                LDSM_X4(aa[mi], sA + off);
            }
            const int bcol = ks * 16 + b_colh;
#pragma unroll
            for (int ni = 0; ni < 4; ni++) {
                const uint32_t off = (uint32_t)(b_row + ni * 8) * 144 + bcol * 2;
                LDSM_X2(bb[ni], sB + off);
            }
#pragma unroll
            for (int mi = 0; mi < 4; mi++)
#pragma unroll
                for (int ni = 0; ni < 4; ni++)
                    MMA_F16(acc[mi][ni], aa[mi], bb[ni][0], bb[ni][1]);
        }
        __syncthreads();
    }

#pragma unroll
    for (int mi = 0; mi < 4; mi++) {
        const int row = m0 + wm * 64 + mi * 16 + (lane >> 2);
#pragma unroll
        for (int ni = 0; ni < 4; ni++) {
            const int col = n0 + wn * 32 + ni * 8 + (lane & 3) * 2;
            float* p0 = C + (size_t)row * ldc + col;
            float* p1 = C + (size_t)(row + 8) * ldc + col;
            if (col < Nreal)     { p0[0] = acc[mi][ni][0]; p1[0] = acc[mi][ni][2]; }
            if (col + 1 < Nreal) { p0[1] = acc[mi][ni][1]; p1[1] = acc[mi][ni][3]; }
        }
    }
}

// ---------------- conversion kernels -------------------------------------------
__device__ __forceinline__ void wsplit16(__half* hi, __half* lo, size_t o, float v) {
    __half h = __float2half_rn(v);
    hi[o] = h;
    lo[o] = __float2half_rn(v - __half2float(h));
}

__global__ void split1h_kernel(const float* __restrict__ in,
                               __half* __restrict__ out, long total)
{
    for (long idx = (long)blockIdx.x * blockDim.x + threadIdx.x; idx < total;
         idx += (long)gridDim.x * blockDim.x)
        out[idx] = __float2half_rn(in[idx]);
}

__global__ void tsplit1h_kernel(const float* __restrict__ W,
                                __half* __restrict__ out,
                                int K, int N, int Kp)
{
    __shared__ float t[32][33];
    int k0 = blockIdx.x * 32, n0 = blockIdx.y * 32;
    for (int i = threadIdx.y; i < 32; i += 8) {
        int k = k0 + i, n = n0 + threadIdx.x;
        t[i][threadIdx.x] = (k < K && n < N) ? W[(size_t)k * N + n] : 0.f;
    }
    __syncthreads();
    for (int i = threadIdx.y; i < 32; i += 8) {
        int n = n0 + i, k = k0 + threadIdx.x;
        out[(size_t)n * Kp + k] = __float2half_rn(t[threadIdx.x][i]);
    }
}

// ---------------- LayerNorm fused with fp16 convert+pad ------------------------
__global__ __launch_bounds__(256) void ln_half_kernel(
    const float* __restrict__ in, const float* __restrict__ w, const float* __restrict__ bb,
    __half* __restrict__ out, int width, int inStride, int wp)
{
    int row = blockIdx.x;
    const float* x = in + (size_t)row * inStride;
    float s = 0.f, s2 = 0.f;
    for (int i = threadIdx.x; i < width; i += 256) { float v = x[i]; s += v; s2 += v * v; }
    __shared__ float sh[64];
#pragma unroll
    for (int o = 16; o > 0; o >>= 1) {
        s  += __shfl_down_sync(0xffffffffu, s,  o);
        s2 += __shfl_down_sync(0xffffffffu, s2, o);
    }
    int wid = threadIdx.x >> 5, lid = threadIdx.x & 31;
    if (lid == 0) { sh[wid] = s; sh[32 + wid] = s2; }
    __syncthreads();
    if (threadIdx.x == 0) {
        float ts = 0.f, ts2 = 0.f;
        for (int i = 0; i < 8; i++) { ts += sh[i]; ts2 += sh[32 + i]; }
        sh[0] = ts; sh[32] = ts2;
    }
    __syncthreads();
    float mean = sh[0] / width;
    float var = sh[32] / width - mean * mean;
    float inv = rsqrtf(var + 1e-5f);
    for (int i = threadIdx.x; i < wp; i += 256) {
        float y = 0.f;
        if (i < width) y = (x[i] - mean) * inv * w[i] + bb[i];
        out[(size_t)row * wp + i] = __float2half_rn(y);
    }
}

// ---------------- RoPE + prep kernels (attention: Q 2xfp16, K/V 1xfp16) --------
__device__ __forceinline__ void rope_cs(int s, int j, float& c, float& sn) {
    float fr = powf(10000.f, -(float)(2 * j) / 128.f);
    float ang = (float)s * fr;
    sn = sinf(ang); c = cosf(ang);
}

__global__ void qprep_kernel(const float* __restrict__ Qf,
                             __half* __restrict__ hi, __half* __restrict__ lo)
{
    int row = blockIdx.x, h = blockIdx.y, j = threadIdx.x;  // 64 threads
    int s = row & (Sseq - 1);
    size_t base = (size_t)row * Dm + h * DHd;
    wsplit16(hi, lo, base + j, Qf[base + j]);
    if (j < 32) {
        float c, sn; rope_cs(s, j, c, sn);
        float x1 = Qf[base + 64 + j], x2 = Qf[base + 96 + j];
        wsplit16(hi, lo, base + 64 + j, x1 * c - x2 * sn);
        wsplit16(hi, lo, base + 96 + j, x2 * c + x1 * sn);
    }
}

__global__ void kprep_kernel(const float* __restrict__ KVf, const float* __restrict__ ckv,
                             __half* __restrict__ K16)
{
    int row = blockIdx.x, h = blockIdx.y, j = threadIdx.x;  // 64 threads
    int s = row & (Sseq - 1);
    size_t ob = (size_t)row * Dm + h * DHd;
    K16[ob + j] = __float2half_rn(KVf[(size_t)row * KVUP_W + h * 192 + j]);
    if (j < 32) {
        float c, sn; rope_cs(s, j, c, sn);
        const float* src = ckv + (size_t)row * CKV_W + KVP;
        float x1 = src[j], x2 = src[j + 32];
        K16[ob + 64 + j] = __float2half_rn(x1 * c - x2 * sn);
        K16[ob + 96 + j] = __float2half_rn(x2 * c + x1 * sn);
    }
}

__global__ void vprep_kernel(const float* __restrict__ KVf, __half* __restrict__ V16)
{
    int row = blockIdx.x, h = blockIdx.y, d = threadIdx.x;  // 128 threads
    V16[(size_t)row * Dm + h * DHd + d] =
        __float2half_rn(KVf[(size_t)row * KVUP_W + h * 192 + 64 + d]);
}

// ---------------- HMMA flash attention (Q 2-term, K/V 1-term, fp16 out) --------
#define AQ_H 0
#define AQ_L 20480
#define AKV  40960
#define KV_STRIDE 37888           // K 20480 + V 17408 per stage
#define A_SS 116736
#define A_PH 134144
#define A_PL 143360
#define A_M  152576
#define A_L  152832
#define A_A  153088
#define ATT_SMEM 153344

__global__ __launch_bounds__(256) void attn_hmma(
    const __half* __restrict__ Qh, const __half* __restrict__ Ql,
    const __half* __restrict__ K16, const __half* __restrict__ V16,
    __half* __restrict__ O)
{
    extern __shared__ char sm[];
    const uint32_t sb = smem_u32(sm);
    float* mrow = (float*)(sm + A_M);
    float* lrow = (float*)(sm + A_L);
    float* arow = (float*)(sm + A_A);
    float* Ss   = (float*)(sm + A_SS);

    const int qt = blockIdx.x, h = blockIdx.y, b = blockIdx.z;
    const int q0 = qt * 64;
    const int tid = threadIdx.x, lane = tid & 31, wid = tid >> 5;
    const int wm = wid >> 1, wn = wid & 1;
    const float scale = 0.08838834764831845f;

    {
        const __half* g0[2] = { Qh, Ql };
#pragma unroll
        for (int part = 0; part < 2; part++) {
            const uint32_t base = sb + AQ_H + part * 20480;
#pragma unroll
            for (int i = 0; i < 4; i++) {
                int idx = tid + i * 256;
                int r = idx >> 4, s = idx & 15;
                uint32_t sa = base + (s >> 2) * 5120 + r * 80 + (s & 3) * 16;
                const __half* g = g0[part] + (size_t)(b * Sseq + q0 + r) * Dm + h * DHd + s * 8;
                CP_ASYNC16(sa, g);
            }
        }
    }

    auto issue_kv = [&](int kt) {
        const int k0 = kt * 64;
        const uint32_t stg = sb + AKV + (uint32_t)(kt & 1) * KV_STRIDE;
        const uint32_t kb = stg, vb = stg + 20480;
#pragma unroll
        for (int i = 0; i < 4; i++) {
            int idx = tid + i * 256;
            int r = idx >> 4, s = idx & 15;
            size_t grow = (size_t)(b * Sseq + k0 + r) * Dm + h * DHd + s * 8;
            CP_ASYNC16(kb + (s >> 2) * 5120 + r * 80 + (s & 3) * 16, K16 + grow);
            CP_ASYNC16(vb + r * 272 + s * 16, V16 + grow);
        }
        CP_COMMIT();
    };

    if (tid < 64) { mrow[tid] = -INFINITY; lrow[tid] = 0.f; }

    float o[8][4];
#pragma unroll
    for (int i = 0; i < 8; i++)
#pragma unroll
        for (int j = 0; j < 4; j++) o[i][j] = 0.f;

    const int nkt = qt + 1;
    issue_kv(0);

    for (int kt = 0; kt < nkt; kt++) {
        const int k0 = kt * 64;
        if (kt + 1 < nkt) { issue_kv(kt + 1); CP_WAIT(1); }
        else              { CP_WAIT(0); }
        __syncthreads();

        const uint32_t stg = sb + AKV + (uint32_t)(kt & 1) * KV_STRIDE;
        const uint32_t sK = stg, sV = stg + 20480;

        float s4[4][4];
#pragma unroll
        for (int i = 0; i < 4; i++)
#pragma unroll
            for (int j = 0; j < 4; j++) s4[i][j] = 0.f;

#pragma unroll
        for (int ks = 0; ks < 8; ks++) {
            uint32_t ah[4], al[4], bb[4][2];
            const int chunk = ks >> 1;
            const uint32_t aoff = (uint32_t)(wm * 16 + (lane & 15)) * 80 +
                                  ((ks & 1) * 16 + ((lane >> 4) << 3)) * 2;
            LDSM_X4(ah, sb + AQ_H + chunk * 5120 + aoff);
            LDSM_X4(al, sb + AQ_L + chunk * 5120 + aoff);
#pragma unroll
            for (int nf = 0; nf < 4; nf++) {
                const uint32_t boff = (uint32_t)(wn * 32 + nf * 8 + (lane & 7)) * 80 +
                                      ((ks & 1) * 16 + (((lane >> 3) & 1) << 3)) * 2;
                LDSM_X2(bb[nf], sK + chunk * 5120 + boff);
            }
#pragma unroll
            for (int nf = 0; nf < 4; nf++) MMA_F16(s4[nf], ah, bb[nf][0], bb[nf][1]);
#pragma unroll
            for (int nf = 0; nf < 4; nf++) MMA_F16(s4[nf], al, bb[nf][0], bb[nf][1]);
        }
        {
            const int r0 = wm * 16 + (lane >> 2);
#pragma unroll
            for (int nf = 0; nf < 4; nf++) {
                const int c0 = wn * 32 + nf * 8 + (lane & 3) * 2;
#pragma unroll
                for (int e = 0; e < 4; e++) {
                    int r = r0 + (e >> 1) * 8;
                    int c = c0 + (e & 1);
                    float v = (k0 + c <= q0 + r) ? s4[nf][e] * scale : -INFINITY;
                    Ss[r * 68 + c] = v;
                }
            }
        }
        __syncthreads();

        {
            const int r = tid >> 2, cs = (tid & 3) * 16;
            float mx = -INFINITY;
#pragma unroll
            for (int j = 0; j < 16; j++) mx = fmaxf(mx, Ss[r * 68 + cs + j]);
            mx = fmaxf(mx, __shfl_xor_sync(0xffffffffu, mx, 1));
            mx = fmaxf(mx, __shfl_xor_sync(0xffffffffu, mx, 2));
            float mold = mrow[r];
            float mnew = fmaxf(mold, mx);
            float sum = 0.f;
            __half* Ph = (__half*)(sm + A_PH);
            __half* Pl = (__half*)(sm + A_PL);
#pragma unroll
            for (int j = 0; j < 16; j++) {
                float p = __expf(Ss[r * 68 + cs + j] - mnew);
                sum += p;
                __half ph = __float2half_rn(p);
                Ph[r * 72 + cs + j] = ph;
                Pl[r * 72 + cs + j] = __float2half_rn(p - __half2float(ph));
            }
            sum += __shfl_xor_sync(0xffffffffu, sum, 1);
            sum += __shfl_xor_sync(0xffffffffu, sum, 2);
            if ((tid & 3) == 0) {
                float alpha = __expf(mold - mnew);
                arow[r] = alpha;
                lrow[r] = lrow[r] * alpha + sum;
                mrow[r] = mnew;
            }
        }
        __syncthreads();

        {
            float al0 = arow[wm * 16 + (lane >> 2)];
            float al1 = arow[wm * 16 + (lane >> 2) + 8];
#pragma unroll
            for (int nf = 0; nf < 8; nf++) {
                o[nf][0] *= al0; o[nf][1] *= al0;
                o[nf][2] *= al1; o[nf][3] *= al1;
            }
        }

#pragma unroll
        for (int ks = 0; ks < 4; ks++) {
            uint32_t ah[4], al[4], bv[8][2];
            const uint32_t aoff = (uint32_t)(wm * 16 + (lane & 15)) * 144 +
                                  (ks * 16 + ((lane >> 4) << 3)) * 2;
            LDSM_X4(ah, sb + A_PH + aoff);
            LDSM_X4(al, sb + A_PL + aoff);
            const int vrow = ks * 16 + (lane & 7) + ((lane >> 3) & 1) * 8;
#pragma unroll
            for (int nf = 0; nf < 8; nf++) {
                const uint32_t boff = (uint32_t)vrow * 272 + (wn * 64 + nf * 8) * 2;
                LDSM_X2_T(bv[nf], sV + boff);
            }
#pragma unroll
            for (int nf = 0; nf < 8; nf++) MMA_F16(o[nf], ah, bv[nf][0], bv[nf][1]);
#pragma unroll
            for (int nf = 0; nf < 8; nf++) MMA_F16(o[nf], al, bv[nf][0], bv[nf][1]);
        }
        __syncthreads();
    }

    {
        const int r0 = wm * 16 + (lane >> 2);
        const float inv0 = 1.f / lrow[r0];
        const float inv1 = 1.f / lrow[r0 + 8];
#pragma unroll
        for (int nf = 0; nf < 8; nf++) {
            const int c = wn * 64 + nf * 8 + (lane & 3) * 2;
            size_t g0 = (size_t)(b * Sseq + q0 + r0) * Dm + h * DHd + c;
            size_t g1 = (size_t)(b * Sseq + q0 + r0 + 8) * Dm + h * DHd + c;
            O[g0]     = __float2half_rn(o[nf][0] * inv0);
            O[g0 + 1] = __float2half_rn(o[nf][1] * inv0);
            O[g1]     = __float2half_rn(o[nf][2] * inv1);
            O[g1 + 1] = __float2half_rn(o[nf][3] * inv1);
        }
    }
}

// ---------------- host launcher -------------------------------------------------
extern "C" void kernel_launch(void* const* d_in, const int* in_sizes, int n_in,
                              void* d_out, int out_size)
{
    const float* query   = (const float*)d_in[0];
    const float* W_dq    = (const float*)d_in[1];
    const float* W_uq    = (const float*)d_in[2];
    const float* q_ln_w  = (const float*)d_in[3];
    const float* q_ln_b  = (const float*)d_in[4];
    const float* W_dkv   = (const float*)d_in[5];
    const float* W_ukv   = (const float*)d_in[6];
    const float* kv_ln_w = (const float*)d_in[7];
    const float* kv_ln_b = (const float*)d_in[8];
    const float* W_o     = (const float*)d_in[9];

    float* out = (float*)d_out;
    float* ckv = out + (size_t)ROWS * Dm;

    __half *q16, *cq16, *kv16, *ao16;
    __half *wdq, *wuq, *wdkv, *wukv, *wo;
    __half *Qhb, *Qlb, *K16, *V16;
    float *cq, *Qf, *KVf;
    cudaGetSymbolAddress((void**)&q16, g_q16);
    cudaGetSymbolAddress((void**)&cq, g_cq);
    cudaGetSymbolAddress((void**)&cq16, g_cq16);
    cudaGetSymbolAddress((void**)&Qf, g_Q);
    cudaGetSymbolAddress((void**)&kv16, g_kv16);
    cudaGetSymbolAddress((void**)&KVf, g_KV);
    cudaGetSymbolAddress((void**)&ao16, g_ao16);
    cudaGetSymbolAddress((void**)&Qhb, g_Qhb);     cudaGetSymbolAddress((void**)&Qlb, g_Qlb);
    cudaGetSymbolAddress((void**)&K16, g_K16);     cudaGetSymbolAddress((void**)&V16, g_V16);
    cudaGetSymbolAddress((void**)&wdq, g_wdq16);   cudaGetSymbolAddress((void**)&wuq, g_wuq16);
    cudaGetSymbolAddress((void**)&wdkv, g_wdkv16); cudaGetSymbolAddress((void**)&wukv, g_wukv16);
    cudaGetSymbolAddress((void**)&wo, g_wo16);

    cudaFuncSetAttribute(hmma_gemm, cudaFuncAttributeMaxDynamicSharedMemorySize, GEMM_SMEM);
    cudaFuncSetAttribute(attn_hmma, cudaFuncAttributeMaxDynamicSharedMemorySize, ATT_SMEM);

    static cudaStream_t s2 = 0;
    static cudaEvent_t evFork = 0, evJoin = 0;
    if (s2 == 0) {
        cudaStreamCreateWithFlags(&s2, cudaStreamNonBlocking);
        cudaEventCreateWithFlags(&evFork, cudaEventDisableTiming);
        cudaEventCreateWithFlags(&evJoin, cudaEventDisableTiming);
    }

    // ---- stream 0 (legacy): q path. launch index 3 = hmma_gemm (ncu target)
    {
        long tq = (long)ROWS * Dm;
        split1h_kernel<<<(int)((tq + 255) / 256), 256>>>(query, q16, tq);            // 0
    }
    cudaEventRecord(evFork, 0);
    tsplit1h_kernel<<<dim3(Dm / 32, QP / 32), dim3(32, 8)>>>(W_dq, wdq, Dm, QP, Dm);  // 1
    tsplit1h_kernel<<<dim3(QP / 32, Dm / 32), dim3(32, 8)>>>(W_uq, wuq, QP, Dm, QP);  // 2
    hmma_gemm<<<dim3(QP / 128, ROWS / 128), 256, GEMM_SMEM>>>(q16, wdq, cq, Dm, QP, QP); // 3 <- ncu
    ln_half_kernel<<<ROWS, 256>>>(cq, q_ln_w, q_ln_b, cq16, QP, QP, QP);
    hmma_gemm<<<dim3(Dm / 128, ROWS / 128), 256, GEMM_SMEM>>>(cq16, wuq, Qf, QP, Dm, Dm);
    qprep_kernel<<<dim3(ROWS, Hh), 64, 0>>>(Qf, Qhb, Qlb);

    // ---- stream s2: kv path (depends only on q16 via evFork)
    cudaStreamWaitEvent(s2, evFork, 0);
    tsplit1h_kernel<<<dim3(Dm / 32, CKV_NPAD / 32), dim3(32, 8), 0, s2>>>(W_dkv, wdkv, Dm, CKV_W, Dm);
    hmma_gemm<<<dim3(CKV_NPAD / 128, ROWS / 128), 256, GEMM_SMEM, s2>>>(q16, wdkv, ckv, Dm, CKV_W, CKV_W);
    ln_half_kernel<<<ROWS, 256, 0, s2>>>(ckv, kv_ln_w, kv_ln_b, kv16, KVP, CKV_W, KVP_PAD);
    tsplit1h_kernel<<<dim3(KVP_PAD / 32, KVUP_W / 32), dim3(32, 8), 0, s2>>>(W_ukv, wukv, KVP, KVUP_W, KVP_PAD);
    hmma_gemm<<<dim3(KVUP_W / 128, ROWS / 128), 256, GEMM_SMEM, s2>>>(kv16, wukv, KVf, KVP_PAD, KVUP_W, KVUP_W);
    kprep_kernel<<<dim3(ROWS, Hh), 64, 0, s2>>>(KVf, ckv, K16);
    vprep_kernel<<<dim3(ROWS, Hh), 128, 0, s2>>>(KVf, V16);
    {
        long tw = (long)Dm * Dm;
        split1h_kernel<<<(int)((tw + 255) / 256), 256, 0, s2>>>(W_o, wo, tw);
    }
    cudaEventRecord(evJoin, s2);

    // ---- join on stream 0: attention + output projection
    cudaStreamWaitEvent(0, evJoin, 0);
    attn_hmma<<<dim3(Sseq / 64, Hh, Bsz), 256, ATT_SMEM>>>(Qhb, Qlb, K16, V16, ao16);
    hmma_gemm<<<dim3(Dm / 128, ROWS / 128), 256, GEMM_SMEM>>>(ao16, wo, out, Dm, Dm, Dm);
}

// round 17
// speedup vs baseline: 1.9369x; 1.1549x over previous
#include <cuda_runtime.h>
#include <cuda_fp16.h>
#include <math.h>
#include <stdint.h>

#define Bsz 2
#define Sseq 2048
#define Dm 2048
#define Hh 16
#define DHd 128
#define QP 1024
#define KVP 1365
#define ROPE 64
#define CKV_W (KVP + ROPE)    // 1429
#define KVUP_W (Dm + Hh * 64) // 3072
#define ROWS (Bsz * Sseq)     // 4096
#define KVP_PAD 1408
#define CKV_NPAD 1536

// ---------------- scratch (device globals; no allocations) ------------------
__device__ __align__(256) __half g_q16  [(size_t)ROWS * Dm];
__device__ __align__(256) float  g_cq   [(size_t)ROWS * QP];
__device__ __align__(256) __half g_cq16 [(size_t)ROWS * QP];
__device__ __align__(256) float  g_Q    [(size_t)ROWS * Dm];
__device__ __align__(256) __half g_kv16 [(size_t)ROWS * KVP_PAD];
__device__ __align__(256) float  g_KV   [(size_t)ROWS * KVUP_W];
__device__ __align__(256) __half g_ao16 [(size_t)ROWS * Dm];
// attention operand buffers (fp16; Q hi/lo, K and V single), [row][h*128+d]
__device__ __align__(256) __half g_Qhb[(size_t)ROWS * Dm];
__device__ __align__(256) __half g_Qlb[(size_t)ROWS * Dm];
__device__ __align__(256) __half g_K16[(size_t)ROWS * Dm];
__device__ __align__(256) __half g_V16[(size_t)ROWS * Dm];
// weights: single fp16, transposed [N][Kp]
__device__ __align__(256) __half g_wdq16 [(size_t)QP * Dm];
__device__ __align__(256) __half g_wuq16 [(size_t)Dm * QP];
__device__ __align__(256) __half g_wdkv16[(size_t)CKV_NPAD * Dm];
__device__ __align__(256) __half g_wukv16[(size_t)KVUP_W * KVP_PAD];
__device__ __align__(256) __half g_wo16  [(size_t)Dm * Dm];

// ---------------- PTX helpers -------------------------------------------------
__device__ __forceinline__ uint32_t smem_u32(const void* p) {
    uint32_t a;
    asm("{ .reg .u64 t; cvta.to.shared.u64 t, %1; cvt.u32.u64 %0, t; }" : "=r"(a) : "l"(p));
    return a;
}
#define LDSM_X4(r, ad) \
    asm volatile("ldmatrix.sync.aligned.m8n8.x4.shared.b16 {%0,%1,%2,%3}, [%4];" \
        : "=r"((r)[0]), "=r"((r)[1]), "=r"((r)[2]), "=r"((r)[3]) : "r"(ad))
#define LDSM_X2(r, ad) \
    asm volatile("ldmatrix.sync.aligned.m8n8.x2.shared.b16 {%0,%1}, [%2];" \
        : "=r"((r)[0]), "=r"((r)[1]) : "r"(ad))
#define LDSM_X2_T(r, ad) \
    asm volatile("ldmatrix.sync.aligned.m8n8.x2.trans.shared.b16 {%0,%1}, [%2];" \
        : "=r"((r)[0]), "=r"((r)[1]) : "r"(ad))
#define MMA_F16(d, a, b0, b1) \
    asm volatile("mma.sync.aligned.m16n8k16.row.col.f32.f16.f16.f32 " \
        "{%0,%1,%2,%3},{%4,%5,%6,%7},{%8,%9},{%0,%1,%2,%3};" \
        : "+f"((d)[0]), "+f"((d)[1]), "+f"((d)[2]), "+f"((d)[3]) \
        : "r"((a)[0]), "r"((a)[1]), "r"((a)[2]), "r"((a)[3]), "r"(b0), "r"(b1))
#define CP_ASYNC16(sa, ga) \
    asm volatile("cp.async.cg.shared.global [%0], [%1], 16;" :: "r"(sa), "l"(ga))
#define CP_COMMIT() asm volatile("cp.async.commit_group;" ::: "memory")
#define CP_WAIT(n)  asm volatile("cp.async.wait_group %0;" :: "n"(n) : "memory")

// ---------------- HMMA fp16 GEMM: A 1x fp16, B 1x fp16, 2 CTAs/SM --------------
#define TILE_BYTES 18432          // 128 rows * 144B (64 halves + 16B pad)
#define STG_BYTES  (2 * TILE_BYTES)
#define GEMM_SMEM  (2 * STG_BYTES)   // 73728

__global__ __launch_bounds__(256, 2) void hmma_gemm(
    const __half* __restrict__ A, const __half* __restrict__ B,
    float* __restrict__ C, int Kp, int Nreal, int ldc)
{
    extern __shared__ char smm[];
    const uint32_t sbase = smem_u32(smm);
    const int tid = threadIdx.x, lane = tid & 31, wid = tid >> 5;
    const int m0 = blockIdx.y * 128, n0 = blockIdx.x * 128;
    const int wm = wid >> 2, wn = wid & 3;
    const __half* srcs[2] = { A, B };

    float acc[4][4][4];
#pragma unroll
    for (int i = 0; i < 4; i++)
#pragma unroll
        for (int j = 0; j < 4; j++)
#pragma unroll
            for (int q = 0; q < 4; q++) acc[i][j][q] = 0.f;

    const int nch = Kp >> 6;

    auto issue = [&](int c) {
        const int s = c & 1;
        const int k0 = c << 6;
#pragma unroll
        for (int t = 0; t < 2; t++) {
            const int row0 = (t == 0) ? m0 : n0;
            const uint32_t sb = sbase + (uint32_t)s * STG_BYTES + (uint32_t)t * TILE_BYTES;
#pragma unroll
            for (int it = 0; it < 4; it++) {
                const int idx = tid + it * 256;
                const int r = idx >> 3, seg = idx & 7;
                CP_ASYNC16(sb + r * 144 + seg * 16,
                           srcs[t] + (size_t)(row0 + r) * Kp + k0 + seg * 8);
            }
        }
        CP_COMMIT();
    };

    issue(0);

    const int a_row = wm * 64 + (lane & 15);
    const int a_colh = (lane >> 4) << 3;
    const int b_row = wn * 32 + (lane & 7);
    const int b_colh = (((lane >> 3) & 1) << 3);

    for (int c = 0; c < nch; c++) {
        const int s = c & 1;
        if (c + 1 < nch) { issue(c + 1); CP_WAIT(1); }
        else             { CP_WAIT(0); }
        __syncthreads();

        const uint32_t sA = sbase + (uint32_t)s * STG_BYTES;
        const uint32_t sB = sA + TILE_BYTES;

#pragma unroll
        for (int ks = 0; ks < 4; ks++) {
            uint32_t aa[4][4], bb[4][2];
            const int acol = ks * 16 + a_colh;
#pragma unroll
            for (int mi = 0; mi < 4; mi++) {
                const uint32_t off = (uint32_t)(a_row + mi * 16) * 144 + acol * 2;
                LDSM_X4(aa[mi], sA + off);
            }
            const int bcol = ks * 16 + b_colh;
#pragma unroll
            for (int ni = 0; ni < 4; ni++) {
                const uint32_t off = (uint32_t)(b_row + ni * 8) * 144 + bcol * 2;
                LDSM_X2(bb[ni], sB + off);
            }
#pragma unroll
            for (int mi = 0; mi < 4; mi++)
#pragma unroll
                for (int ni = 0; ni < 4; ni++)
                    MMA_F16(acc[mi][ni], aa[mi], bb[ni][0], bb[ni][1]);
        }
        __syncthreads();
    }

#pragma unroll
    for (int mi = 0; mi < 4; mi++) {
        const int row = m0 + wm * 64 + mi * 16 + (lane >> 2);
#pragma unroll
        for (int ni = 0; ni < 4; ni++) {
            const int col = n0 + wn * 32 + ni * 8 + (lane & 3) * 2;
            float* p0 = C + (size_t)row * ldc + col;
            float* p1 = C + (size_t)(row + 8) * ldc + col;
            if (col < Nreal)     { p0[0] = acc[mi][ni][0]; p1[0] = acc[mi][ni][2]; }
            if (col + 1 < Nreal) { p0[1] = acc[mi][ni][1]; p1[1] = acc[mi][ni][3]; }
        }
    }
}

// ---------------- conversion kernels -------------------------------------------
__device__ __forceinline__ void wsplit16(__half* hi, __half* lo, size_t o, float v) {
    __half h = __float2half_rn(v);
    hi[o] = h;
    lo[o] = __float2half_rn(v - __half2float(h));
}

__global__ void split1h_kernel(const float* __restrict__ in,
                               __half* __restrict__ out, long total)
{
    for (long idx = (long)blockIdx.x * blockDim.x + threadIdx.x; idx < total;
         idx += (long)gridDim.x * blockDim.x)
        out[idx] = __float2half_rn(in[idx]);
}

__global__ void tsplit1h_kernel(const float* __restrict__ W,
                                __half* __restrict__ out,
                                int K, int N, int Kp)
{
    __shared__ float t[32][33];
    int k0 = blockIdx.x * 32, n0 = blockIdx.y * 32;
    for (int i = threadIdx.y; i < 32; i += 8) {
        int k = k0 + i, n = n0 + threadIdx.x;
        t[i][threadIdx.x] = (k < K && n < N) ? W[(size_t)k * N + n] : 0.f;
    }
    __syncthreads();
    for (int i = threadIdx.y; i < 32; i += 8) {
        int n = n0 + i, k = k0 + threadIdx.x;
        out[(size_t)n * Kp + k] = __float2half_rn(t[threadIdx.x][i]);
    }
}

// ---------------- LayerNorm fused with fp16 convert+pad ------------------------
__global__ __launch_bounds__(256) void ln_half_kernel(
    const float* __restrict__ in, const float* __restrict__ w, const float* __restrict__ bb,
    __half* __restrict__ out, int width, int inStride, int wp)
{
    int row = blockIdx.x;
    const float* x = in + (size_t)row * inStride;
    float s = 0.f, s2 = 0.f;
    for (int i = threadIdx.x; i < width; i += 256) { float v = x[i]; s += v; s2 += v * v; }
    __shared__ float sh[64];
#pragma unroll
    for (int o = 16; o > 0; o >>= 1) {
        s  += __shfl_down_sync(0xffffffffu, s,  o);
        s2 += __shfl_down_sync(0xffffffffu, s2, o);
    }
    int wid = threadIdx.x >> 5, lid = threadIdx.x & 31;
    if (lid == 0) { sh[wid] = s; sh[32 + wid] = s2; }
    __syncthreads();
    if (threadIdx.x == 0) {
        float ts = 0.f, ts2 = 0.f;
        for (int i = 0; i < 8; i++) { ts += sh[i]; ts2 += sh[32 + i]; }
        sh[0] = ts; sh[32] = ts2;
    }
    __syncthreads();
    float mean = sh[0] / width;
    float var = sh[32] / width - mean * mean;
    float inv = rsqrtf(var + 1e-5f);
    for (int i = threadIdx.x; i < wp; i += 256) {
        float y = 0.f;
        if (i < width) y = (x[i] - mean) * inv * w[i] + bb[i];
        out[(size_t)row * wp + i] = __float2half_rn(y);
    }
}

// ---------------- RoPE + prep kernels (attention: Q 2xfp16, K/V 1xfp16) --------
__device__ __forceinline__ void rope_cs(int s, int j, float& c, float& sn) {
    float fr = powf(10000.f, -(float)(2 * j) / 128.f);
    float ang = (float)s * fr;
    sn = sinf(ang); c = cosf(ang);
}

__global__ void qprep_kernel(const float* __restrict__ Qf,
                             __half* __restrict__ hi, __half* __restrict__ lo)
{
    int row = blockIdx.x, h = blockIdx.y, j = threadIdx.x;  // 64 threads
    int s = row & (Sseq - 1);
    size_t base = (size_t)row * Dm + h * DHd;
    wsplit16(hi, lo, base + j, Qf[base + j]);
    if (j < 32) {
        float c, sn; rope_cs(s, j, c, sn);
        float x1 = Qf[base + 64 + j], x2 = Qf[base + 96 + j];
        wsplit16(hi, lo, base + 64 + j, x1 * c - x2 * sn);
        wsplit16(hi, lo, base + 96 + j, x2 * c + x1 * sn);
    }
}

__global__ void kprep_kernel(const float* __restrict__ KVf, const float* __restrict__ ckv,
                             __half* __restrict__ K16)
{
    int row = blockIdx.x, h = blockIdx.y, j = threadIdx.x;  // 64 threads
    int s = row & (Sseq - 1);
    size_t ob = (size_t)row * Dm + h * DHd;
    K16[ob + j] = __float2half_rn(KVf[(size_t)row * KVUP_W + h * 192 + j]);
    if (j < 32) {
        float c, sn; rope_cs(s, j, c, sn);
        const float* src = ckv + (size_t)row * CKV_W + KVP;
        float x1 = src[j], x2 = src[j + 32];
        K16[ob + 64 + j] = __float2half_rn(x1 * c - x2 * sn);
        K16[ob + 96 + j] = __float2half_rn(x2 * c + x1 * sn);
    }
}

__global__ void vprep_kernel(const float* __restrict__ KVf, __half* __restrict__ V16)
{
    int row = blockIdx.x, h = blockIdx.y, d = threadIdx.x;  // 128 threads
    V16[(size_t)row * Dm + h * DHd + d] =
        __float2half_rn(KVf[(size_t)row * KVUP_W + h * 192 + 64 + d]);
}

// ---------------- HMMA flash attention (Q 2-term, K/V/P 1-term) ----------------
#define AQ_H 0
#define AQ_L 20480
#define AKV  40960
#define KV_STRIDE 37888           // K 20480 + V 17408 per stage
#define A_SS 116736
#define A_PH 134144
#define A_M  152576
#define A_L  152832
#define A_A  153088
#define ATT_SMEM 153344

__global__ __launch_bounds__(256) void attn_hmma(
    const __half* __restrict__ Qh, const __half* __restrict__ Ql,
    const __half* __restrict__ K16, const __half* __restrict__ V16,
    __half* __restrict__ O)
{
    extern __shared__ char sm[];
    const uint32_t sb = smem_u32(sm);
    float* mrow = (float*)(sm + A_M);
    float* lrow = (float*)(sm + A_L);
    float* arow = (float*)(sm + A_A);
    float* Ss   = (float*)(sm + A_SS);

    const int qt = blockIdx.x, h = blockIdx.y, b = blockIdx.z;
    const int q0 = qt * 64;
    const int tid = threadIdx.x, lane = tid & 31, wid = tid >> 5;
    const int wm = wid >> 1, wn = wid & 1;
    const float scale = 0.08838834764831845f;

    {
        const __half* g0[2] = { Qh, Ql };
#pragma unroll
        for (int part = 0; part < 2; part++) {
            const uint32_t base = sb + AQ_H + part * 20480;
#pragma unroll
            for (int i = 0; i < 4; i++) {
                int idx = tid + i * 256;
                int r = idx >> 4, s = idx & 15;
                uint32_t sa = base + (s >> 2) * 5120 + r * 80 + (s & 3) * 16;
                const __half* g = g0[part] + (size_t)(b * Sseq + q0 + r) * Dm + h * DHd + s * 8;
                CP_ASYNC16(sa, g);
            }
        }
    }

    auto issue_kv = [&](int kt) {
        const int k0 = kt * 64;
        const uint32_t stg = sb + AKV + (uint32_t)(kt & 1) * KV_STRIDE;
        const uint32_t kb = stg, vb = stg + 20480;
#pragma unroll
        for (int i = 0; i < 4; i++) {
            int idx = tid + i * 256;
            int r = idx >> 4, s = idx & 15;
            size_t grow = (size_t)(b * Sseq + k0 + r) * Dm + h * DHd + s * 8;
            CP_ASYNC16(kb + (s >> 2) * 5120 + r * 80 + (s & 3) * 16, K16 + grow);
            CP_ASYNC16(vb + r * 272 + s * 16, V16 + grow);
        }
        CP_COMMIT();
    };

    if (tid < 64) { mrow[tid] = -INFINITY; lrow[tid] = 0.f; }

    float o[8][4];
#pragma unroll
    for (int i = 0; i < 8; i++)
#pragma unroll
        for (int j = 0; j < 4; j++) o[i][j] = 0.f;

    const int nkt = qt + 1;
    issue_kv(0);

    for (int kt = 0; kt < nkt; kt++) {
        const int k0 = kt * 64;
        if (kt + 1 < nkt) { issue_kv(kt + 1); CP_WAIT(1); }
        else              { CP_WAIT(0); }
        __syncthreads();

        const uint32_t stg = sb + AKV + (uint32_t)(kt & 1) * KV_STRIDE;
        const uint32_t sK = stg, sV = stg + 20480;

        float s4[4][4];
#pragma unroll
        for (int i = 0; i < 4; i++)
#pragma unroll
            for (int j = 0; j < 4; j++) s4[i][j] = 0.f;

#pragma unroll
        for (int ks = 0; ks < 8; ks++) {
            uint32_t ah[4], al[4], bb[4][2];
            const int chunk = ks >> 1;
            const uint32_t aoff = (uint32_t)(wm * 16 + (lane & 15)) * 80 +
                                  ((ks & 1) * 16 + ((lane >> 4) << 3)) * 2;
            LDSM_X4(ah, sb + AQ_H + chunk * 5120 + aoff);
            LDSM_X4(al, sb + AQ_L + chunk * 5120 + aoff);
#pragma unroll
            for (int nf = 0; nf < 4; nf++) {
                const uint32_t boff = (uint32_t)(wn * 32 + nf * 8 + (lane & 7)) * 80 +
                                      ((ks & 1) * 16 + (((lane >> 3) & 1) << 3)) * 2;
                LDSM_X2(bb[nf], sK + chunk * 5120 + boff);
            }
#pragma unroll
            for (int nf = 0; nf < 4; nf++) MMA_F16(s4[nf], ah, bb[nf][0], bb[nf][1]);
#pragma unroll
            for (int nf = 0; nf < 4; nf++) MMA_F16(s4[nf], al, bb[nf][0], bb[nf][1]);
        }
        {
            const int r0 = wm * 16 + (lane >> 2);
#pragma unroll
            for (int nf = 0; nf < 4; nf++) {
                const int c0 = wn * 32 + nf * 8 + (lane & 3) * 2;
#pragma unroll
                for (int e = 0; e < 4; e++) {
                    int r = r0 + (e >> 1) * 8;
                    int c = c0 + (e & 1);
                    float v = (k0 + c <= q0 + r) ? s4[nf][e] * scale : -INFINITY;
                    Ss[r * 68 + c] = v;
                }
            }
        }
        __syncthreads();

        {
            const int r = tid >> 2, cs = (tid & 3) * 16;
            float mx = -INFINITY;
#pragma unroll
            for (int j = 0; j < 16; j++) mx = fmaxf(mx, Ss[r * 68 + cs + j]);
            mx = fmaxf(mx, __shfl_xor_sync(0xffffffffu, mx, 1));
            mx = fmaxf(mx, __shfl_xor_sync(0xffffffffu, mx, 2));
            float mold = mrow[r];
            float mnew = fmaxf(mold, mx);
            float sum = 0.f;
            __half* Ph = (__half*)(sm + A_PH);
#pragma unroll
            for (int j = 0; j < 16; j++) {
                float p = __expf(Ss[r * 68 + cs + j] - mnew);
                sum += p;
                Ph[r * 72 + cs + j] = __float2half_rn(p);
            }
            sum += __shfl_xor_sync(0xffffffffu, sum, 1);
            sum += __shfl_xor_sync(0xffffffffu, sum, 2);
            if ((tid & 3) == 0) {
                float alpha = __expf(mold - mnew);
                arow[r] = alpha;
                lrow[r] = lrow[r] * alpha + sum;
                mrow[r] = mnew;
            }
        }
        __syncthreads();

        {
            float al0 = arow[wm * 16 + (lane >> 2)];
            float al1 = arow[wm * 16 + (lane >> 2) + 8];
#pragma unroll
            for (int nf = 0; nf < 8; nf++) {
                o[nf][0] *= al0; o[nf][1] *= al0;
                o[nf][2] *= al1; o[nf][3] *= al1;
            }
        }

#pragma unroll
        for (int ks = 0; ks < 4; ks++) {
            uint32_t ap[4], bv[8][2];
            const uint32_t aoff = (uint32_t)(wm * 16 + (lane & 15)) * 144 +
                                  (ks * 16 + ((lane >> 4) << 3)) * 2;
            LDSM_X4(ap, sb + A_PH + aoff);
            const int vrow = ks * 16 + (lane & 7) + ((lane >> 3) & 1) * 8;
#pragma unroll
            for (int nf = 0; nf < 8; nf++) {
                const uint32_t boff = (uint32_t)vrow * 272 + (wn * 64 + nf * 8) * 2;
                LDSM_X2_T(bv[nf], sV + boff);
            }
#pragma unroll
            for (int nf = 0; nf < 8; nf++) MMA_F16(o[nf], ap, bv[nf][0], bv[nf][1]);
        }
        __syncthreads();
    }

    {
        const int r0 = wm * 16 + (lane >> 2);
        const float inv0 = 1.f / lrow[r0];
        const float inv1 = 1.f / lrow[r0 + 8];
#pragma unroll
        for (int nf = 0; nf < 8; nf++) {
            const int c = wn * 64 + nf * 8 + (lane & 3) * 2;
            size_t g0 = (size_t)(b * Sseq + q0 + r0) * Dm + h * DHd + c;
            size_t g1 = (size_t)(b * Sseq + q0 + r0 + 8) * Dm + h * DHd + c;
            O[g0]     = __float2half_rn(o[nf][0] * inv0);
            O[g0 + 1] = __float2half_rn(o[nf][1] * inv0);
            O[g1]     = __float2half_rn(o[nf][2] * inv1);
            O[g1 + 1] = __float2half_rn(o[nf][3] * inv1);
        }
    }
}

// ---------------- host launcher -------------------------------------------------
extern "C" void kernel_launch(void* const* d_in, const int* in_sizes, int n_in,
                              void* d_out, int out_size)
{
    const float* query   = (const float*)d_in[0];
    const float* W_dq    = (const float*)d_in[1];
    const float* W_uq    = (const float*)d_in[2];
    const float* q_ln_w  = (const float*)d_in[3];
    const float* q_ln_b  = (const float*)d_in[4];
    const float* W_dkv   = (const float*)d_in[5];
    const float* W_ukv   = (const float*)d_in[6];
    const float* kv_ln_w = (const float*)d_in[7];
    const float* kv_ln_b = (const float*)d_in[8];
    const float* W_o     = (const float*)d_in[9];

    float* out = (float*)d_out;
    float* ckv = out + (size_t)ROWS * Dm;

    __half *q16, *cq16, *kv16, *ao16;
    __half *wdq, *wuq, *wdkv, *wukv, *wo;
    __half *Qhb, *Qlb, *K16, *V16;
    float *cq, *Qf, *KVf;
    cudaGetSymbolAddress((void**)&q16, g_q16);
    cudaGetSymbolAddress((void**)&cq, g_cq);
    cudaGetSymbolAddress((void**)&cq16, g_cq16);
    cudaGetSymbolAddress((void**)&Qf, g_Q);
    cudaGetSymbolAddress((void**)&kv16, g_kv16);
    cudaGetSymbolAddress((void**)&KVf, g_KV);
    cudaGetSymbolAddress((void**)&ao16, g_ao16);
    cudaGetSymbolAddress((void**)&Qhb, g_Qhb);     cudaGetSymbolAddress((void**)&Qlb, g_Qlb);
    cudaGetSymbolAddress((void**)&K16, g_K16);     cudaGetSymbolAddress((void**)&V16, g_V16);
    cudaGetSymbolAddress((void**)&wdq, g_wdq16);   cudaGetSymbolAddress((void**)&wuq, g_wuq16);
    cudaGetSymbolAddress((void**)&wdkv, g_wdkv16); cudaGetSymbolAddress((void**)&wukv, g_wukv16);
    cudaGetSymbolAddress((void**)&wo, g_wo16);

    cudaFuncSetAttribute(hmma_gemm, cudaFuncAttributeMaxDynamicSharedMemorySize, GEMM_SMEM);
    cudaFuncSetAttribute(attn_hmma, cudaFuncAttributeMaxDynamicSharedMemorySize, ATT_SMEM);

    static cudaStream_t s2 = 0;
    static cudaEvent_t evFork = 0, evJoin = 0;
    if (s2 == 0) {
        cudaStreamCreateWithFlags(&s2, cudaStreamNonBlocking);
        cudaEventCreateWithFlags(&evFork, cudaEventDisableTiming);
        cudaEventCreateWithFlags(&evJoin, cudaEventDisableTiming);
    }

    // ---- stream 0 (legacy): q path. launch index 3 = hmma_gemm (ncu target)
    {
        long tq = (long)ROWS * Dm;
        split1h_kernel<<<(int)((tq + 255) / 256), 256>>>(query, q16, tq);            // 0
    }
    cudaEventRecord(evFork, 0);
    tsplit1h_kernel<<<dim3(Dm / 32, QP / 32), dim3(32, 8)>>>(W_dq, wdq, Dm, QP, Dm);  // 1
    tsplit1h_kernel<<<dim3(QP / 32, Dm / 32), dim3(32, 8)>>>(W_uq, wuq, QP, Dm, QP);  // 2
    hmma_gemm<<<dim3(QP / 128, ROWS / 128), 256, GEMM_SMEM>>>(q16, wdq, cq, Dm, QP, QP); // 3 <- ncu
    ln_half_kernel<<<ROWS, 256>>>(cq, q_ln_w, q_ln_b, cq16, QP, QP, QP);
    hmma_gemm<<<dim3(Dm / 128, ROWS / 128), 256, GEMM_SMEM>>>(cq16, wuq, Qf, QP, Dm, Dm);
    qprep_kernel<<<dim3(ROWS, Hh), 64, 0>>>(Qf, Qhb, Qlb);

    // ---- stream s2: kv path (depends only on q16 via evFork)
    cudaStreamWaitEvent(s2, evFork, 0);
    tsplit1h_kernel<<<dim3(Dm / 32, CKV_NPAD / 32), dim3(32, 8), 0, s2>>>(W_dkv, wdkv, Dm, CKV_W, Dm);
    hmma_gemm<<<dim3(CKV_NPAD / 128, ROWS / 128), 256, GEMM_SMEM, s2>>>(q16, wdkv, ckv, Dm, CKV_W, CKV_W);
    ln_half_kernel<<<ROWS, 256, 0, s2>>>(ckv, kv_ln_w, kv_ln_b, kv16, KVP, CKV_W, KVP_PAD);
    tsplit1h_kernel<<<dim3(KVP_PAD / 32, KVUP_W / 32), dim3(32, 8), 0, s2>>>(W_ukv, wukv, KVP, KVUP_W, KVP_PAD);
    hmma_gemm<<<dim3(KVUP_W / 128, ROWS / 128), 256, GEMM_SMEM, s2>>>(kv16, wukv, KVf, KVP_PAD, KVUP_W, KVUP_W);
    kprep_kernel<<<dim3(ROWS, Hh), 64, 0, s2>>>(KVf, ckv, K16);
    vprep_kernel<<<dim3(ROWS, Hh), 128, 0, s2>>>(KVf, V16);
    {
        long tw = (long)Dm * Dm;
        split1h_kernel<<<(int)((tw + 255) / 256), 256, 0, s2>>>(W_o, wo, tw);
    }
    cudaEventRecord(evJoin, s2);

    // ---- join on stream 0: attention + output projection
    cudaStreamWaitEvent(0, evJoin, 0);
    attn_hmma<<<dim3(Sseq / 64, Hh, Bsz), 256, ATT_SMEM>>>(Qhb, Qlb, K16, V16, ao16);
    hmma_gemm<<<dim3(Dm / 128, ROWS / 128), 256, GEMM_SMEM>>>(ao16, wo, out, Dm, Dm, Dm);
}